// round 8
// baseline (speedup 1.0000x reference)
#include <cuda_runtime.h>
#include <cuda_bf16.h>
#include <cstdint>

// Problem constants
#define NROWS 65536   // 32 * 2048
#define DIMS  512
#define CODES 1024

#define MT  128       // rows per CTA (TC kernel)
#define NT2 128       // codes per tile
#define KC  32        // K floats per staged chunk (bf16-packed: 16 u32/row)
#define NCH (DIMS / KC)      // 16 chunks
#define NTL (CODES / NT2)    // 8 tiles

#define MARGIN 1.0e-3f       // ~17 sigma of bf16 score-error; exact fallback covers flags

// Scratch (device globals — allocation is forbidden)
__device__ float g_enorm[CODES];
__device__ float g_znorm[NROWS];
__device__ int   g_flagcnt;
__device__ int   g_flagrows[NROWS];
__device__ unsigned long long g_best[NROWS];

// ---------------------------------------------------------------------------
// Helpers
// ---------------------------------------------------------------------------
__device__ __forceinline__ void mma_bf16(float* c,
                                         uint32_t a0, uint32_t a1, uint32_t a2, uint32_t a3,
                                         uint32_t b0, uint32_t b1) {
    asm volatile(
        "mma.sync.aligned.m16n8k16.row.col.f32.bf16.bf16.f32 "
        "{%0,%1,%2,%3}, {%4,%5,%6,%7}, {%8,%9}, {%0,%1,%2,%3};"
        : "+f"(c[0]), "+f"(c[1]), "+f"(c[2]), "+f"(c[3])
        : "r"(a0), "r"(a1), "r"(a2), "r"(a3), "r"(b0), "r"(b1));
}

// swizzled u32 index in a [128][16]-u32 tile: (r, c) -> r*16 + 4*((c>>2)^((r>>1)&3)) + (c&3)
__device__ __forceinline__ int swz(int r, int c) {
    return (r << 4) + ((((c >> 2) ^ ((r >> 1) & 3)) & 3) << 2) + (c & 3);
}

__device__ __forceinline__ uint32_t pack_bf16x2(float lo, float hi) {
    __nv_bfloat162 p = __float22bfloat162_rn(make_float2(lo, hi));  // .x -> low half
    return *reinterpret_cast<uint32_t*>(&p);
}

// ---------------------------------------------------------------------------
// Norm kernels (fp64 accumulate -> fp32), one warp per row
// ---------------------------------------------------------------------------
__global__ void enorm_kernel(const float* __restrict__ emb) {
    if (blockIdx.x == 0 && threadIdx.x == 0) g_flagcnt = 0;  // reset per replay
    int warp = (blockIdx.x * blockDim.x + threadIdx.x) >> 5;
    int lane = threadIdx.x & 31;
    if (warp >= CODES) return;
    const float4* row = reinterpret_cast<const float4*>(emb + (size_t)warp * DIMS);
    double s = 0.0;
#pragma unroll
    for (int i = 0; i < 4; i++) {
        float4 v = row[lane + i * 32];
        s += (double)v.x * v.x + (double)v.y * v.y
           + (double)v.z * v.z + (double)v.w * v.w;
    }
#pragma unroll
    for (int off = 16; off > 0; off >>= 1)
        s += __shfl_xor_sync(0xffffffffu, s, off);
    if (lane == 0) g_enorm[warp] = (float)s;
}

__global__ void znorm_kernel(const float* __restrict__ z) {
    int warp = (blockIdx.x * blockDim.x + threadIdx.x) >> 5;
    int lane = threadIdx.x & 31;
    if (warp >= NROWS) return;
    const float4* row = reinterpret_cast<const float4*>(z + (size_t)warp * DIMS);
    double s = 0.0;
#pragma unroll
    for (int i = 0; i < 4; i++) {
        float4 v = row[lane + i * 32];
        s += (double)v.x * v.x + (double)v.y * v.y
           + (double)v.z * v.z + (double)v.w * v.w;
    }
#pragma unroll
    for (int off = 16; off > 0; off >>= 1)
        s += __shfl_xor_sync(0xffffffffu, s, off);
    if (lane == 0) g_znorm[warp] = (float)s;
}

// ---------------------------------------------------------------------------
// TC kernel: single-pass bf16 mma.sync (k16) + top-2 argmin + flag + gather
// ---------------------------------------------------------------------------
__global__ __launch_bounds__(256, 2)
void vq_mma_kernel(const float* __restrict__ z,
                   const float* __restrict__ emb,
                   float* __restrict__ out) {
    __shared__ __align__(16) uint32_t sA[128 * 16];   // 8 KB bf16-packed
    __shared__ __align__(16) uint32_t sB[128 * 16];   // 8 KB
    __shared__ float sbest[128 * 4];
    __shared__ float sb2  [128 * 4];
    __shared__ int   sidn [128 * 4];
    __shared__ int   srow [128];

    const int t    = threadIdx.x;
    const int lane = t & 31;
    const int wid  = t >> 5;
    const int row0 = blockIdx.x * MT;
    const int wm = (wid & 1) * 64;
    const int wn = (wid >> 1) * 32;
    const int lr4 = lane >> 2;
    const int lc  = lane & 3;

    float zn[8];
#pragma unroll
    for (int mi = 0; mi < 4; mi++)
#pragma unroll
        for (int h = 0; h < 2; h++)
            zn[mi * 2 + h] = g_znorm[row0 + wm + mi * 16 + lr4 + h * 8];

    float best[8], b2[8];
    int   bidx[8];
#pragma unroll
    for (int i = 0; i < 8; i++) { best[i] = 3.4e38f; b2[i] = 3.4e38f; bidx[i] = 0; }

    for (int nt = 0; nt < NTL; nt++) {
        const int n0 = nt * NT2;

        float acc[4][4][4];
#pragma unroll
        for (int mi = 0; mi < 4; mi++)
#pragma unroll
            for (int nj = 0; nj < 4; nj++)
#pragma unroll
                for (int q = 0; q < 4; q++) acc[mi][nj][q] = 0.f;

        // prefetch chunk 0: 4 float4 per thread per tile (128 rows x 32 floats)
        float4 pa[4], pb[4];
#pragma unroll
        for (int i = 0; i < 4; i++) {
            int v = t + 256 * i;
            int r = v >> 3, q = v & 7;
            pa[i] = *reinterpret_cast<const float4*>(z   + (size_t)(row0 + r) * DIMS + q * 4);
            pb[i] = *reinterpret_cast<const float4*>(emb + (size_t)(n0  + r) * DIMS + q * 4);
        }

        for (int c = 0; c < NCH; c++) {
            __syncthreads();
            // ---- convert + store (2 packed u32 per float4, STS.64) ----
#pragma unroll
            for (int i = 0; i < 4; i++) {
                int v = t + 256 * i;
                int r = v >> 3, q = v & 7;
                int idx = swz(r, q * 2);     // q*2 and q*2+1 share the swizzle group
                uint2 w;
                w.x = pack_bf16x2(pa[i].x, pa[i].y);
                w.y = pack_bf16x2(pa[i].z, pa[i].w);
                *reinterpret_cast<uint2*>(&sA[idx]) = w;
                w.x = pack_bf16x2(pb[i].x, pb[i].y);
                w.y = pack_bf16x2(pb[i].z, pb[i].w);
                *reinterpret_cast<uint2*>(&sB[idx]) = w;
            }
            __syncthreads();

            // ---- prefetch next chunk ----
            if (c + 1 < NCH) {
                const int k0n = (c + 1) * KC;
#pragma unroll
                for (int i = 0; i < 4; i++) {
                    int v = t + 256 * i;
                    int r = v >> 3, q = v & 7;
                    pa[i] = *reinterpret_cast<const float4*>(
                        z   + (size_t)(row0 + r) * DIMS + k0n + q * 4);
                    pb[i] = *reinterpret_cast<const float4*>(
                        emb + (size_t)(n0  + r) * DIMS + k0n + q * 4);
                }
            }

            // ---- 2 k16-steps ----
#pragma unroll
            for (int ks = 0; ks < 2; ks++) {
                uint32_t B[4][2];
#pragma unroll
                for (int nj = 0; nj < 4; nj++) {
                    int n = wn + nj * 8 + lr4;
                    B[nj][0] = sB[swz(n, ks * 8 + lc)];
                    B[nj][1] = sB[swz(n, ks * 8 + lc + 4)];
                }
#pragma unroll
                for (int mi = 0; mi < 4; mi++) {
                    int r = wm + mi * 16 + lr4;
                    uint32_t A0 = sA[swz(r,     ks * 8 + lc)];
                    uint32_t A1 = sA[swz(r + 8, ks * 8 + lc)];
                    uint32_t A2 = sA[swz(r,     ks * 8 + lc + 4)];
                    uint32_t A3 = sA[swz(r + 8, ks * 8 + lc + 4)];
#pragma unroll
                    for (int nj = 0; nj < 4; nj++)
                        mma_bf16(acc[mi][nj], A0, A1, A2, A3, B[nj][0], B[nj][1]);
                }
            }
        }

        // ---- epilogue: ref-rounding score + running top-2 ----
#pragma unroll
        for (int mi = 0; mi < 4; mi++) {
#pragma unroll
            for (int nj = 0; nj < 4; nj++) {
                int cbase = n0 + wn + nj * 8 + 2 * lc;
                float en0 = __ldg(&g_enorm[cbase]);
                float en1 = __ldg(&g_enorm[cbase + 1]);
                const float* cc = acc[mi][nj];
#pragma unroll
                for (int h = 0; h < 2; h++) {
                    int s0i = mi * 2 + h;
                    float s0 = __fsub_rn(__fadd_rn(zn[s0i], en0), __fmul_rn(2.0f, cc[h * 2]));
                    float s1 = __fsub_rn(__fadd_rn(zn[s0i], en1), __fmul_rn(2.0f, cc[h * 2 + 1]));
                    if (s0 < best[s0i]) { b2[s0i] = best[s0i]; best[s0i] = s0; bidx[s0i] = cbase; }
                    else if (s0 < b2[s0i]) b2[s0i] = s0;
                    if (s1 < best[s0i]) { b2[s0i] = best[s0i]; best[s0i] = s1; bidx[s0i] = cbase + 1; }
                    else if (s1 < b2[s0i]) b2[s0i] = s1;
                }
            }
        }
    }

    // ---- cross-lane top-2 merge ----
#pragma unroll
    for (int s = 0; s < 8; s++) {
#pragma unroll
        for (int off = 1; off <= 2; off <<= 1) {
            float vb  = __shfl_xor_sync(0xffffffffu, best[s], off);
            float vb2 = __shfl_xor_sync(0xffffffffu, b2[s],   off);
            int   vi  = __shfl_xor_sync(0xffffffffu, bidx[s], off);
            if (vb < best[s]) { b2[s] = fminf(best[s], vb2); best[s] = vb; bidx[s] = vi; }
            else if (vb > best[s]) { b2[s] = fminf(b2[s], vb); }
            else { bidx[s] = min(bidx[s], vi); b2[s] = vb; }
        }
    }
    __syncthreads();
    if (lc == 0) {
#pragma unroll
        for (int mi = 0; mi < 4; mi++)
#pragma unroll
            for (int h = 0; h < 2; h++) {
                int r = wm + mi * 16 + lr4 + h * 8;
                sbest[r * 4 + (wid >> 1)] = best[mi * 2 + h];
                sb2  [r * 4 + (wid >> 1)] = b2  [mi * 2 + h];
                sidn [r * 4 + (wid >> 1)] = bidx[mi * 2 + h];
            }
    }
    __syncthreads();

    if (t < 128) {
        float b  = sbest[t * 4];
        float bb = sb2  [t * 4];
        int   bi = sidn [t * 4];
#pragma unroll
        for (int x = 1; x < 4; x++) {
            float v  = sbest[t * 4 + x];
            float v2 = sb2  [t * 4 + x];
            int   vi = sidn [t * 4 + x];
            if (v < b) { bb = fminf(b, v2); b = v; bi = vi; }
            else if (v > b) { bb = fminf(bb, v); }
            else { bi = min(bi, vi); bb = v; }
        }
        srow[t] = bi;
        if (__fsub_rn(bb, b) < MARGIN) {   // ambiguous -> exact recompute
            int row = row0 + t;
            g_best[row] = ~0ULL;
            int p = atomicAdd(&g_flagcnt, 1);
            g_flagrows[p] = row;
        }
    }
    __syncthreads();

    // ---- gather: out[row] = emb[idx] (flagged rows fixed later) ----
    float4*       out4 = reinterpret_cast<float4*>(out + (size_t)row0 * DIMS);
    const float4* emb4 = reinterpret_cast<const float4*>(emb);
    for (int v = t; v < 128 * (DIMS / 4); v += 256) {
        int r  = v >> 7;
        int c4 = v & 127;
        out4[(size_t)r * 128 + c4] = emb4[(size_t)srow[r] * 128 + c4];
    }
}

// ---------------------------------------------------------------------------
// Exact fallback: R2-identical arithmetic for flagged rows.
// ---------------------------------------------------------------------------
__global__ __launch_bounds__(256)
void vq_exact_kernel(const float* __restrict__ z,
                     const float* __restrict__ emb) {
    __shared__ float Zs[16 * 64];
    __shared__ float Es[16 * 128];
    __shared__ int   rlist[64];

    const int t  = threadIdx.x;
    const int tx = t & 15;    // 8 codes each
    const int ty = t >> 4;    // 4 rows each

    int cnt = g_flagcnt;
    if (cnt <= 0) return;
    int tb = (cnt + 63) >> 6;
    int total = tb * 8;

    for (int task = blockIdx.x; task < total; task += gridDim.x) {
        int rb = task >> 3;
        int cg = task & 7;
        int c0 = cg * 128;

        __syncthreads();
        if (t < 64) {
            int j = rb * 64 + t;
            rlist[t] = g_flagrows[j < cnt ? j : cnt - 1];
        }
        __syncthreads();

        float zn[4];
        int rows[4];
#pragma unroll
        for (int i = 0; i < 4; i++) {
            rows[i] = rlist[ty * 4 + i];
            zn[i] = g_znorm[rows[i]];
        }
        float en[8];
#pragma unroll
        for (int j = 0; j < 8; j++) en[j] = g_enorm[c0 + tx * 8 + j];

        float acc[4][8];
#pragma unroll
        for (int i = 0; i < 4; i++)
#pragma unroll
            for (int j = 0; j < 8; j++) acc[i][j] = 0.f;

        for (int c = 0; c < 32; c++) {      // 32 x 16-float chunks (R2 ordering)
            const int k0 = c * 16;
            __syncthreads();
            {   // stage Z: 64 rows x 16 K, [k][row]
                int r = t >> 2, q = t & 3;
                float4 x = *reinterpret_cast<const float4*>(
                    z + (size_t)rlist[r] * DIMS + k0 + q * 4);
                Zs[(q * 4 + 0) * 64 + r] = x.x;
                Zs[(q * 4 + 1) * 64 + r] = x.y;
                Zs[(q * 4 + 2) * 64 + r] = x.z;
                Zs[(q * 4 + 3) * 64 + r] = x.w;
            }
#pragma unroll
            for (int i = 0; i < 2; i++) {   // stage E: 128 codes x 16 K
                int v = t + 256 * i;
                int r = v >> 2, q = v & 3;
                float4 x = *reinterpret_cast<const float4*>(
                    emb + (size_t)(c0 + r) * DIMS + k0 + q * 4);
                Es[(q * 4 + 0) * 128 + r] = x.x;
                Es[(q * 4 + 1) * 128 + r] = x.y;
                Es[(q * 4 + 2) * 128 + r] = x.z;
                Es[(q * 4 + 3) * 128 + r] = x.w;
            }
            __syncthreads();

#pragma unroll
            for (int k = 0; k < 16; k++) {
                float zf[4], ef[8];
#pragma unroll
                for (int i = 0; i < 4; i++) zf[i] = Zs[k * 64 + ty * 4 + i];
#pragma unroll
                for (int j = 0; j < 8; j++) ef[j] = Es[k * 128 + tx * 8 + j];
#pragma unroll
                for (int i = 0; i < 4; i++)
#pragma unroll
                    for (int j = 0; j < 8; j++)
                        acc[i][j] = fmaf(zf[i], ef[j], acc[i][j]);
            }
        }

        // score + per-thread argmin (codes ascending -> strict < keeps lowest)
#pragma unroll
        for (int i = 0; i < 4; i++) {
            float bb = 3.4e38f;
            int   bi = 0;
#pragma unroll
            for (int j = 0; j < 8; j++) {
                float s = __fsub_rn(__fadd_rn(zn[i], en[j]),
                                    __fmul_rn(2.0f, acc[i][j]));
                if (s < bb) { bb = s; bi = c0 + tx * 8 + j; }
            }
            unsigned long long pk =
                ((unsigned long long)__float_as_uint(bb) << 32) | (unsigned)bi;
#pragma unroll
            for (int off = 1; off <= 8; off <<= 1) {
                unsigned long long o = __shfl_xor_sync(0xffffffffu, pk, off);
                if (o < pk) pk = o;
            }
            if (tx == 0) atomicMin(&g_best[rows[i]], pk);
        }
    }
}

// ---------------------------------------------------------------------------
// Fixup gather for flagged rows
// ---------------------------------------------------------------------------
__global__ void vq_fix_kernel(const float* __restrict__ emb,
                              float* __restrict__ out) {
    int cnt = g_flagcnt;
    for (int j = blockIdx.x; j < cnt; j += gridDim.x) {
        int row = g_flagrows[j];
        unsigned idx = (unsigned)(g_best[row] & 0xffffffffu);
        const float4* src = reinterpret_cast<const float4*>(emb + (size_t)idx * DIMS);
        float4*       dst = reinterpret_cast<float4*>(out + (size_t)row * DIMS);
        for (int v = threadIdx.x; v < DIMS / 4; v += blockDim.x)
            dst[v] = src[v];
    }
}

// ---------------------------------------------------------------------------
// Launch
// ---------------------------------------------------------------------------
extern "C" void kernel_launch(void* const* d_in, const int* in_sizes, int n_in,
                              void* d_out, int out_size) {
    const float* z   = (const float*)d_in[0];   // [32,2048,512] fp32
    const float* emb = (const float*)d_in[1];   // [1024,512] fp32
    float* out = (float*)d_out;

    enorm_kernel<<<(CODES * 32 + 255) / 256, 256>>>(emb);   // also resets flagcnt
    znorm_kernel<<<(NROWS * 32 + 255) / 256, 256>>>(z);
    vq_mma_kernel<<<NROWS / MT, 256>>>(z, emb, out);
    vq_exact_kernel<<<1024, 256>>>(z, emb);
    vq_fix_kernel<<<256, 128>>>(emb, out);
}

// round 9
// speedup vs baseline: 1.4529x; 1.4529x over previous
#include <cuda_runtime.h>
#include <cuda_fp16.h>
#include <cstdint>
#include <cfloat>

// Problem constants
#define NROWS 65536   // 32 * 2048
#define DIMS  512
#define CODES 1024

#define MT   128      // rows per CTA (TC kernel)
#define NT2  128      // codes per tile
#define KC   32       // K floats per staged chunk (fp16-packed: 16 u32/row)
#define NCH  (DIMS / KC)     // 16 chunks
#define NTL  (CODES / NT2)   // 8 tiles

#define MARGIN 2.0e-4f       // ~13 sigma of fp16 score error

// Scratch (device globals — allocation is forbidden)
__device__ float g_enorm[CODES];
__device__ float g_znorm[NROWS];
__device__ int   g_flagcnt;
__device__ int   g_flagrows[NROWS];
__device__ unsigned long long g_best[NROWS];

// ---------------------------------------------------------------------------
// Helpers
// ---------------------------------------------------------------------------
__device__ __forceinline__ void mma_f16(float* c,
                                        uint32_t a0, uint32_t a1, uint32_t a2, uint32_t a3,
                                        uint32_t b0, uint32_t b1) {
    asm volatile(
        "mma.sync.aligned.m16n8k16.row.col.f32.f16.f16.f32 "
        "{%0,%1,%2,%3}, {%4,%5,%6,%7}, {%8,%9}, {%0,%1,%2,%3};"
        : "+f"(c[0]), "+f"(c[1]), "+f"(c[2]), "+f"(c[3])
        : "r"(a0), "r"(a1), "r"(a2), "r"(a3), "r"(b0), "r"(b1));
}

__device__ __forceinline__ void ldsm_x4(uint32_t* f, uint32_t addr) {
    asm volatile(
        "ldmatrix.sync.aligned.m8n8.x4.shared.b16 {%0,%1,%2,%3}, [%4];"
        : "=r"(f[0]), "=r"(f[1]), "=r"(f[2]), "=r"(f[3]) : "r"(addr));
}

// byte offset of the 16B group (row r, u32-group g) in a swizzled [128][16]-u32 tile
__device__ __forceinline__ uint32_t swz_grp(int r, int g) {
    int xr = (r >> 1) & 3;
    return (uint32_t)(((r << 4) + (((g ^ xr) & 3) << 2)) << 2);
}

__device__ __forceinline__ uint32_t pack_h2(float lo, float hi) {
    __half2 p = __float22half2_rn(make_float2(lo, hi));   // .x -> low 16 bits
    return *reinterpret_cast<uint32_t*>(&p);
}

// ---------------------------------------------------------------------------
// enorm: ||e_k||^2 (fp64 -> fp32), one warp per code row; resets flagcnt
// ---------------------------------------------------------------------------
__global__ void enorm_kernel(const float* __restrict__ emb) {
    if (blockIdx.x == 0 && threadIdx.x == 0) g_flagcnt = 0;
    int warp = (blockIdx.x * blockDim.x + threadIdx.x) >> 5;
    int lane = threadIdx.x & 31;
    if (warp >= CODES) return;
    const float4* row = reinterpret_cast<const float4*>(emb + (size_t)warp * DIMS);
    double s = 0.0;
#pragma unroll
    for (int i = 0; i < 4; i++) {
        float4 v = row[lane + i * 32];
        s += (double)v.x * v.x + (double)v.y * v.y
           + (double)v.z * v.z + (double)v.w * v.w;
    }
#pragma unroll
    for (int off = 16; off > 0; off >>= 1)
        s += __shfl_xor_sync(0xffffffffu, s, off);
    if (lane == 0) g_enorm[warp] = (float)s;
}

// ---------------------------------------------------------------------------
// TC kernel: fp16 mma.sync (k16) + ldmatrix + dbuffer + top-2 + flag + gather
// 512 threads: 16 warps = 2 (M: 64 rows) x 8 (N: 16 codes)
// ---------------------------------------------------------------------------
__global__ __launch_bounds__(512, 1)
void vq_mma_kernel(const float* __restrict__ z,
                   const float* __restrict__ emb,
                   float* __restrict__ out) {
    __shared__ __align__(16) uint32_t sA[2][2048];   // 2 x 8KB fp16-packed
    __shared__ __align__(16) uint32_t sB[2][2048];
    __shared__ float znr[128];
    __shared__ float sen[128];
    __shared__ float sbest[128 * 8];
    __shared__ float sb2  [128 * 8];
    __shared__ int   sidn [128 * 8];
    __shared__ int   srow [128];

    const int t    = threadIdx.x;
    const int lane = t & 31;
    const int wid  = t >> 5;
    const int row0 = blockIdx.x * MT;
    const int wm   = (wid & 1) * 64;
    const int wcol = wid >> 1;          // 0..7
    const int wn   = wcol * 16;
    const int lr4  = lane >> 2;
    const int lc   = lane & 3;

    // ldmatrix per-lane address components
    const int m8 = lane >> 3, l7 = lane & 7;
    const int arow_off = ((m8 & 1) << 3) + l7;   // + wm + mi*16
    const int ag_off   = m8 >> 1;                // + 2*ks
    const int brow     = wn + ((m8 >> 1) << 3) + l7;
    const int bg_off   = m8 & 1;                 // + 2*ks

    const uint32_t sAb = (uint32_t)__cvta_generic_to_shared(&sA[0][0]);
    const uint32_t sBb = (uint32_t)__cvta_generic_to_shared(&sB[0][0]);

    // init running top-2 slots
    for (int i = t; i < 128 * 8; i += 512) {
        sbest[i] = FLT_MAX; sb2[i] = FLT_MAX; sidn[i] = 0;
    }

    // ---- fused znorm (fp64, identical algorithm to the proven R2 kernel) ----
#pragma unroll
    for (int rr = 0; rr < 8; rr++) {
        int row = wid * 8 + rr;
        const float4* rp = reinterpret_cast<const float4*>(z + (size_t)(row0 + row) * DIMS);
        double s = 0.0;
#pragma unroll
        for (int i = 0; i < 4; i++) {
            float4 v = rp[lane + i * 32];
            s += (double)v.x * v.x + (double)v.y * v.y
               + (double)v.z * v.z + (double)v.w * v.w;
        }
#pragma unroll
        for (int off = 16; off > 0; off >>= 1)
            s += __shfl_xor_sync(0xffffffffu, s, off);
        if (lane == 0) { znr[row] = (float)s; g_znorm[row0 + row] = (float)s; }
    }
    __syncthreads();

    // staging mapping: v = t, t+512 -> (r = v>>3, q = v&7) float4 each per tile
    const int sr0 = t >> 3,          sq0 = t & 7;
    const int sr1 = (t + 512) >> 3,  sq1 = (t + 512) & 7;

    for (int nt = 0; nt < NTL; nt++) {
        const int n0 = nt * NT2;
        if (t < 32)
            reinterpret_cast<float4*>(sen)[t] =
                reinterpret_cast<const float4*>(&g_enorm[n0])[t];

        float acc[4][2][4];
#pragma unroll
        for (int mi = 0; mi < 4; mi++)
#pragma unroll
            for (int nj = 0; nj < 2; nj++)
#pragma unroll
                for (int q = 0; q < 4; q++) acc[mi][nj][q] = 0.f;

        // ---- stage chunk 0 into buf 0 ----
        float4 pa0, pa1, pb0, pb1;
        pa0 = *reinterpret_cast<const float4*>(z   + (size_t)(row0 + sr0) * DIMS + sq0 * 4);
        pa1 = *reinterpret_cast<const float4*>(z   + (size_t)(row0 + sr1) * DIMS + sq1 * 4);
        pb0 = *reinterpret_cast<const float4*>(emb + (size_t)(n0  + sr0) * DIMS + sq0 * 4);
        pb1 = *reinterpret_cast<const float4*>(emb + (size_t)(n0  + sr1) * DIMS + sq1 * 4);
        {
            uint32_t i0 = (swz_grp(sr0, sq0 >> 1) >> 2) + ((sq0 & 1) << 1);
            uint32_t i1 = (swz_grp(sr1, sq1 >> 1) >> 2) + ((sq1 & 1) << 1);
            *reinterpret_cast<uint2*>(&sA[0][i0]) = make_uint2(pack_h2(pa0.x, pa0.y), pack_h2(pa0.z, pa0.w));
            *reinterpret_cast<uint2*>(&sA[0][i1]) = make_uint2(pack_h2(pa1.x, pa1.y), pack_h2(pa1.z, pa1.w));
            *reinterpret_cast<uint2*>(&sB[0][i0]) = make_uint2(pack_h2(pb0.x, pb0.y), pack_h2(pb0.z, pb0.w));
            *reinterpret_cast<uint2*>(&sB[0][i1]) = make_uint2(pack_h2(pb1.x, pb1.y), pack_h2(pb1.z, pb1.w));
        }
        __syncthreads();

        for (int c = 0; c < NCH; c++) {
            const int cur = c & 1;
            // prefetch next chunk (hides under the mma block)
            if (c + 1 < NCH) {
                const int k0 = (c + 1) * KC;
                pa0 = *reinterpret_cast<const float4*>(z   + (size_t)(row0 + sr0) * DIMS + k0 + sq0 * 4);
                pa1 = *reinterpret_cast<const float4*>(z   + (size_t)(row0 + sr1) * DIMS + k0 + sq1 * 4);
                pb0 = *reinterpret_cast<const float4*>(emb + (size_t)(n0  + sr0) * DIMS + k0 + sq0 * 4);
                pb1 = *reinterpret_cast<const float4*>(emb + (size_t)(n0  + sr1) * DIMS + k0 + sq1 * 4);
            }

            const uint32_t bufA = sAb + cur * 8192;
            const uint32_t bufB = sBb + cur * 8192;
#pragma unroll
            for (int ks = 0; ks < 2; ks++) {
                uint32_t B[4];
                ldsm_x4(B, bufB + swz_grp(brow, 2 * ks + bg_off));   // {b0 nj0, b1 nj0, b0 nj1, b1 nj1}
#pragma unroll
                for (int mi = 0; mi < 4; mi++) {
                    uint32_t A[4];
                    ldsm_x4(A, bufA + swz_grp(wm + mi * 16 + arow_off, 2 * ks + ag_off));
                    mma_f16(acc[mi][0], A[0], A[1], A[2], A[3], B[0], B[1]);
                    mma_f16(acc[mi][1], A[0], A[1], A[2], A[3], B[2], B[3]);
                }
            }

            if (c + 1 < NCH) {
                const int nb = cur ^ 1;
                uint32_t i0 = (swz_grp(sr0, sq0 >> 1) >> 2) + ((sq0 & 1) << 1);
                uint32_t i1 = (swz_grp(sr1, sq1 >> 1) >> 2) + ((sq1 & 1) << 1);
                *reinterpret_cast<uint2*>(&sA[nb][i0]) = make_uint2(pack_h2(pa0.x, pa0.y), pack_h2(pa0.z, pa0.w));
                *reinterpret_cast<uint2*>(&sA[nb][i1]) = make_uint2(pack_h2(pa1.x, pa1.y), pack_h2(pa1.z, pa1.w));
                *reinterpret_cast<uint2*>(&sB[nb][i0]) = make_uint2(pack_h2(pb0.x, pb0.y), pack_h2(pb0.z, pb0.w));
                *reinterpret_cast<uint2*>(&sB[nb][i1]) = make_uint2(pack_h2(pb1.x, pb1.y), pack_h2(pb1.z, pb1.w));
            }
            __syncthreads();
        }

        // ---- epilogue: ref-rounding score + tile top-2 + smem merge ----
#pragma unroll
        for (int mi = 0; mi < 4; mi++) {
#pragma unroll
            for (int h = 0; h < 2; h++) {
                int row = wm + mi * 16 + lr4 + 8 * h;
                float znv = znr[row];
                float b = FLT_MAX, b2v = FLT_MAX;
                int   bi = 0;
#pragma unroll
                for (int nj = 0; nj < 2; nj++) {
                    int ce = wn + nj * 8 + 2 * lc;
                    float en0 = sen[ce], en1 = sen[ce + 1];
                    float s0 = __fsub_rn(__fadd_rn(znv, en0), __fmul_rn(2.0f, acc[mi][nj][h * 2]));
                    float s1 = __fsub_rn(__fadd_rn(znv, en1), __fmul_rn(2.0f, acc[mi][nj][h * 2 + 1]));
                    int cb = n0 + ce;
                    if (s0 < b) { b2v = b; b = s0; bi = cb; }
                    else if (s0 < b2v) b2v = s0;
                    if (s1 < b) { b2v = b; b = s1; bi = cb + 1; }
                    else if (s1 < b2v) b2v = s1;
                }
                // merge across the 4 lanes sharing this row (lc group)
#pragma unroll
                for (int off = 1; off <= 2; off <<= 1) {
                    float vb  = __shfl_xor_sync(0xffffffffu, b,   off);
                    float vb2 = __shfl_xor_sync(0xffffffffu, b2v, off);
                    int   vi  = __shfl_xor_sync(0xffffffffu, bi,  off);
                    if (vb < b) { b2v = fminf(b, vb2); b = vb; bi = vi; }
                    else if (vb > b) { b2v = fminf(b2v, vb); }
                    else { bi = min(bi, vi); b2v = vb; }   // exact tie -> gap 0 -> flagged
                }
                if (lc == 0) {
                    int s = row * 8 + wcol;
                    float ob = sbest[s], ob2 = sb2[s];
                    int   oi = sidn[s];
                    if (b < ob)      { sbest[s] = b;  sb2[s] = fminf(ob, b2v);  sidn[s] = bi; }
                    else if (b > ob) {                sb2[s] = fminf(ob2, b);                 }
                    else             {                sb2[s] = ob;              sidn[s] = min(oi, bi); }
                }
            }
        }
        __syncthreads();   // slots settled; sen safe to overwrite next tile
    }

    // ---- final per-row merge + flag ----
    if (t < 128) {
        float b  = sbest[t * 8];
        float bb = sb2  [t * 8];
        int   bi = sidn [t * 8];
#pragma unroll
        for (int x = 1; x < 8; x++) {
            float v  = sbest[t * 8 + x];
            float v2 = sb2  [t * 8 + x];
            int   vi = sidn [t * 8 + x];
            if (v < b) { bb = fminf(b, v2); b = v; bi = vi; }
            else if (v > b) { bb = fminf(bb, v); }
            else { bi = min(bi, vi); bb = v; }
        }
        srow[t] = bi;
        if (__fsub_rn(bb, b) < MARGIN) {
            int row = row0 + t;
            g_best[row] = ~0ULL;
            int p = atomicAdd(&g_flagcnt, 1);
            g_flagrows[p] = row;
        }
    }
    __syncthreads();

    // ---- gather: out[row] = emb[idx] (flagged rows fixed later) ----
    float4*       out4 = reinterpret_cast<float4*>(out + (size_t)row0 * DIMS);
    const float4* emb4 = reinterpret_cast<const float4*>(emb);
    for (int v = t; v < 128 * (DIMS / 4); v += 512) {
        int r  = v >> 7;
        int c4 = v & 127;
        out4[(size_t)r * 128 + c4] = emb4[(size_t)srow[r] * 128 + c4];
    }
}

// ---------------------------------------------------------------------------
// Exact fallback: R2-identical arithmetic, 128 flagged rows x 128 codes/task
// ---------------------------------------------------------------------------
__global__ __launch_bounds__(256)
void vq_exact_kernel(const float* __restrict__ z,
                     const float* __restrict__ emb) {
    __shared__ float Zs[16 * 128];
    __shared__ float Es[16 * 128];
    __shared__ int   rlist[128];

    const int t  = threadIdx.x;
    const int tx = t & 15;    // 8 codes each
    const int ty = t >> 4;    // 8 rows each
    const int lr = t >> 2;    // staging row 0..63 (and +64)
    const int dq = t & 3;

    int cnt = g_flagcnt;
    if (cnt <= 0) return;
    int tb = (cnt + 127) >> 7;
    int total = tb * 8;

    for (int task = blockIdx.x; task < total; task += gridDim.x) {
        int rb = task >> 3;
        int cg = task & 7;
        int c0 = cg * 128;

        __syncthreads();
        if (t < 128) {
            int j = rb * 128 + t;
            rlist[t] = g_flagrows[j < cnt ? j : cnt - 1];
        }
        __syncthreads();

        int rows[8]; float zn[8];
#pragma unroll
        for (int i = 0; i < 8; i++) {
            rows[i] = rlist[ty * 8 + i];
            zn[i] = g_znorm[rows[i]];
        }
        float en[8];
#pragma unroll
        for (int j = 0; j < 8; j++) en[j] = g_enorm[c0 + tx * 8 + j];

        float acc[8][8];
#pragma unroll
        for (int i = 0; i < 8; i++)
#pragma unroll
            for (int j = 0; j < 8; j++) acc[i][j] = 0.f;

        for (int c = 0; c < 32; c++) {       // 32 x 16-float chunks, R2 ordering
            const int k0 = c * 16;
            float4 za = *reinterpret_cast<const float4*>(
                z + (size_t)rlist[lr] * DIMS + k0 + dq * 4);
            float4 zb = *reinterpret_cast<const float4*>(
                z + (size_t)rlist[lr + 64] * DIMS + k0 + dq * 4);
            float4 ea = *reinterpret_cast<const float4*>(
                emb + (size_t)(c0 + lr) * DIMS + k0 + dq * 4);
            float4 eb = *reinterpret_cast<const float4*>(
                emb + (size_t)(c0 + lr + 64) * DIMS + k0 + dq * 4);

            __syncthreads();
            Zs[(dq * 4 + 0) * 128 + lr] = za.x;
            Zs[(dq * 4 + 1) * 128 + lr] = za.y;
            Zs[(dq * 4 + 2) * 128 + lr] = za.z;
            Zs[(dq * 4 + 3) * 128 + lr] = za.w;
            Zs[(dq * 4 + 0) * 128 + lr + 64] = zb.x;
            Zs[(dq * 4 + 1) * 128 + lr + 64] = zb.y;
            Zs[(dq * 4 + 2) * 128 + lr + 64] = zb.z;
            Zs[(dq * 4 + 3) * 128 + lr + 64] = zb.w;
            Es[(dq * 4 + 0) * 128 + lr] = ea.x;
            Es[(dq * 4 + 1) * 128 + lr] = ea.y;
            Es[(dq * 4 + 2) * 128 + lr] = ea.z;
            Es[(dq * 4 + 3) * 128 + lr] = ea.w;
            Es[(dq * 4 + 0) * 128 + lr + 64] = eb.x;
            Es[(dq * 4 + 1) * 128 + lr + 64] = eb.y;
            Es[(dq * 4 + 2) * 128 + lr + 64] = eb.z;
            Es[(dq * 4 + 3) * 128 + lr + 64] = eb.w;
            __syncthreads();

#pragma unroll
            for (int k = 0; k < 16; k++) {
                float zf[8], ef[8];
                *reinterpret_cast<float4*>(zf)     = *reinterpret_cast<float4*>(&Zs[k * 128 + ty * 8]);
                *reinterpret_cast<float4*>(zf + 4) = *reinterpret_cast<float4*>(&Zs[k * 128 + ty * 8 + 4]);
                *reinterpret_cast<float4*>(ef)     = *reinterpret_cast<float4*>(&Es[k * 128 + tx * 8]);
                *reinterpret_cast<float4*>(ef + 4) = *reinterpret_cast<float4*>(&Es[k * 128 + tx * 8 + 4]);
#pragma unroll
                for (int i = 0; i < 8; i++)
#pragma unroll
                    for (int j = 0; j < 8; j++)
                        acc[i][j] = fmaf(zf[i], ef[j], acc[i][j]);
            }
        }

        // score + per-thread argmin + cross-lane packed min (tie -> lowest idx)
#pragma unroll
        for (int i = 0; i < 8; i++) {
            float bb = 3.4e38f;
            int   bi = 0;
#pragma unroll
            for (int j = 0; j < 8; j++) {
                float s = __fsub_rn(__fadd_rn(zn[i], en[j]),
                                    __fmul_rn(2.0f, acc[i][j]));
                if (s < bb) { bb = s; bi = c0 + tx * 8 + j; }
            }
            unsigned long long pk =
                ((unsigned long long)__float_as_uint(bb) << 32) | (unsigned)bi;
#pragma unroll
            for (int off = 1; off <= 8; off <<= 1) {
                unsigned long long o = __shfl_xor_sync(0xffffffffu, pk, off);
                if (o < pk) pk = o;
            }
            if (tx == 0) atomicMin(&g_best[rows[i]], pk);
        }
    }
}

// ---------------------------------------------------------------------------
// Fixup gather for flagged rows
// ---------------------------------------------------------------------------
__global__ void vq_fix_kernel(const float* __restrict__ emb,
                              float* __restrict__ out) {
    int cnt = g_flagcnt;
    for (int j = blockIdx.x; j < cnt; j += gridDim.x) {
        int row = g_flagrows[j];
        unsigned idx = (unsigned)(g_best[row] & 0xffffffffu);
        const float4* src = reinterpret_cast<const float4*>(emb + (size_t)idx * DIMS);
        float4*       dst = reinterpret_cast<float4*>(out + (size_t)row * DIMS);
        for (int v = threadIdx.x; v < DIMS / 4; v += blockDim.x)
            dst[v] = src[v];
    }
}

// ---------------------------------------------------------------------------
// Launch
// ---------------------------------------------------------------------------
extern "C" void kernel_launch(void* const* d_in, const int* in_sizes, int n_in,
                              void* d_out, int out_size) {
    const float* z   = (const float*)d_in[0];   // [32,2048,512] fp32
    const float* emb = (const float*)d_in[1];   // [1024,512] fp32
    float* out = (float*)d_out;

    enorm_kernel<<<(CODES * 32 + 255) / 256, 256>>>(emb);   // also resets flagcnt
    vq_mma_kernel<<<NROWS / MT, 512>>>(z, emb, out);        // znorm fused inside
    vq_exact_kernel<<<1024, 256>>>(z, emb);
    vq_fix_kernel<<<256, 128>>>(emb, out);
}

// round 10
// speedup vs baseline: 1.6247x; 1.1182x over previous
#include <cuda_runtime.h>
#include <cuda_fp16.h>
#include <cstdint>
#include <cfloat>

// Problem constants
#define NROWS 65536   // 32 * 2048
#define DIMS  512
#define CODES 1024

#define MT   128      // rows per CTA (TC kernel)
#define NT2  128      // codes per tile
#define KC   32       // K floats per chunk (fp16: 16 u32 per row)
#define NCH  (DIMS / KC)     // 16 chunks
#define NTL  (CODES / NT2)   // 8 tiles

#define MARGIN 2.0e-4f       // ~13 sigma of fp16 score error

// Scratch (device globals — allocation is forbidden)
__device__ float g_enorm[CODES];
__device__ float g_znorm[NROWS];
__device__ int   g_flagcnt;
__device__ int   g_flagrows[NROWS];
__device__ unsigned long long g_best[NROWS];
__device__ uint32_t g_z16[NROWS * DIMS / 2];   // 64 MB fp16-packed z
__device__ uint32_t g_e16[CODES * DIMS / 2];   // 1 MB fp16-packed emb

// ---------------------------------------------------------------------------
// Helpers
// ---------------------------------------------------------------------------
__device__ __forceinline__ void mma_f16(float* c,
                                        uint32_t a0, uint32_t a1, uint32_t a2, uint32_t a3,
                                        uint32_t b0, uint32_t b1) {
    asm volatile(
        "mma.sync.aligned.m16n8k16.row.col.f32.f16.f16.f32 "
        "{%0,%1,%2,%3}, {%4,%5,%6,%7}, {%8,%9}, {%0,%1,%2,%3};"
        : "+f"(c[0]), "+f"(c[1]), "+f"(c[2]), "+f"(c[3])
        : "r"(a0), "r"(a1), "r"(a2), "r"(a3), "r"(b0), "r"(b1));
}

__device__ __forceinline__ void ldsm_x4(uint32_t* f, uint32_t addr) {
    asm volatile(
        "ldmatrix.sync.aligned.m8n8.x4.shared.b16 {%0,%1,%2,%3}, [%4];"
        : "=r"(f[0]), "=r"(f[1]), "=r"(f[2]), "=r"(f[3]) : "r"(addr));
}

// byte offset of the 16B group (row r, u32-group g) in a swizzled [128][16]-u32 tile
__device__ __forceinline__ uint32_t swz_grp(int r, int g) {
    int xr = (r >> 1) & 3;
    return (uint32_t)(((r << 4) + (((g ^ xr) & 3) << 2)) << 2);
}

__device__ __forceinline__ uint32_t pack_h2(float lo, float hi) {
    __half2 p = __float22half2_rn(make_float2(lo, hi));   // .x -> low 16 bits
    return *reinterpret_cast<uint32_t*>(&p);
}

// ---------------------------------------------------------------------------
// Convert kernels: fp32 -> packed fp16 globals, fused fp64 norms
// (norm algorithm identical to the R2-proven kernel -> bit-identical norms)
// ---------------------------------------------------------------------------
__global__ void econv_kernel(const float* __restrict__ emb) {
    if (blockIdx.x == 0 && threadIdx.x == 0) g_flagcnt = 0;
    int warp = (blockIdx.x * blockDim.x + threadIdx.x) >> 5;
    int lane = threadIdx.x & 31;
    if (warp >= CODES) return;
    const float4* row = reinterpret_cast<const float4*>(emb + (size_t)warp * DIMS);
    double s = 0.0;
#pragma unroll
    for (int i = 0; i < 4; i++) {
        int j = lane + i * 32;
        float4 v = row[j];
        s += (double)v.x * v.x + (double)v.y * v.y
           + (double)v.z * v.z + (double)v.w * v.w;
        uint2 w = make_uint2(pack_h2(v.x, v.y), pack_h2(v.z, v.w));
        *reinterpret_cast<uint2*>(&g_e16[(size_t)warp * 256 + j * 2]) = w;
    }
#pragma unroll
    for (int off = 16; off > 0; off >>= 1)
        s += __shfl_xor_sync(0xffffffffu, s, off);
    if (lane == 0) g_enorm[warp] = (float)s;
}

__global__ void zconv_kernel(const float* __restrict__ z) {
    int warp = (blockIdx.x * blockDim.x + threadIdx.x) >> 5;
    int lane = threadIdx.x & 31;
    if (warp >= NROWS) return;
    const float4* row = reinterpret_cast<const float4*>(z + (size_t)warp * DIMS);
    double s = 0.0;
#pragma unroll
    for (int i = 0; i < 4; i++) {
        int j = lane + i * 32;
        float4 v = row[j];
        s += (double)v.x * v.x + (double)v.y * v.y
           + (double)v.z * v.z + (double)v.w * v.w;
        uint2 w = make_uint2(pack_h2(v.x, v.y), pack_h2(v.z, v.w));
        *reinterpret_cast<uint2*>(&g_z16[(size_t)warp * 256 + j * 2]) = w;
    }
#pragma unroll
    for (int off = 16; off > 0; off >>= 1)
        s += __shfl_xor_sync(0xffffffffu, s, off);
    if (lane == 0) g_znorm[warp] = (float)s;
}

// ---------------------------------------------------------------------------
// TC kernel: fp16 mma.sync (k16), A-tile resident in smem, B double-buffered
// 512 threads: 16 warps = 2 (M: 64 rows) x 8 (N: 16 codes)
// Dynamic smem: A = 16 chunk-tiles x 8KB = 128KB at offset 0; B dbuf at +128KB
// ---------------------------------------------------------------------------
#define SM_A_BYTES (NCH * 8192)            // 131072
#define SM_DYN     (SM_A_BYTES + 2 * 8192) // 147456

extern __shared__ uint32_t dsm[];

__global__ __launch_bounds__(512, 1)
void vq_mma_kernel(const float* __restrict__ emb,
                   float* __restrict__ out) {
    __shared__ float znr[128];
    __shared__ float sen[128];
    __shared__ float sbest[128 * 8];
    __shared__ float sb2  [128 * 8];
    __shared__ int   sidn [128 * 8];
    __shared__ int   srow [128];

    const int t    = threadIdx.x;
    const int lane = t & 31;
    const int wid  = t >> 5;
    const int row0 = blockIdx.x * MT;
    const int wm   = (wid & 1) * 64;
    const int wcol = wid >> 1;          // 0..7
    const int wn   = wcol * 16;
    const int lr4  = lane >> 2;
    const int lc   = lane & 3;

    // ldmatrix per-lane address components
    const int m8 = lane >> 3, l7 = lane & 7;
    const int arow_off = ((m8 & 1) << 3) + l7;   // + wm + mi*16
    const int ag_off   = m8 >> 1;                // + 2*ks
    const int brow     = wn + ((m8 >> 1) << 3) + l7;
    const int bg_off   = m8 & 1;                 // + 2*ks

    const uint32_t sAb = (uint32_t)__cvta_generic_to_shared(dsm);
    const uint32_t sBb = sAb + SM_A_BYTES;

    // staging mapping (both A and B): r = t>>2, 16B group g4 = t&3
    const int sr = t >> 2, sg = t & 3;
    const uint32_t sts_off = swz_grp(sr, sg);    // byte offset within an 8KB tile

    // init reductions + row norms
    for (int i = t; i < 128 * 8; i += 512) {
        sbest[i] = FLT_MAX; sb2[i] = FLT_MAX; sidn[i] = 0;
    }
    if (t < 128) znr[t] = g_znorm[row0 + t];

    // ---- load resident A: 16 chunk-tiles, 1 uint4 per thread per chunk ----
    {
        const uint32_t* zsrc = &g_z16[(size_t)(row0 + sr) * 256 + sg * 4];
        char* sAc = reinterpret_cast<char*>(dsm);
#pragma unroll
        for (int c = 0; c < NCH; c++) {
            uint4 v = *reinterpret_cast<const uint4*>(zsrc + c * 16);
            *reinterpret_cast<uint4*>(sAc + c * 8192 + sts_off) = v;
        }
    }
    __syncthreads();

    char* sBc = reinterpret_cast<char*>(dsm) + SM_A_BYTES;

    for (int nt = 0; nt < NTL; nt++) {
        const int n0 = nt * NT2;
        if (t < 32)
            reinterpret_cast<float4*>(sen)[t] =
                reinterpret_cast<const float4*>(&g_enorm[n0])[t];

        float acc[4][2][4];
#pragma unroll
        for (int mi = 0; mi < 4; mi++)
#pragma unroll
            for (int nj = 0; nj < 2; nj++)
#pragma unroll
                for (int q = 0; q < 4; q++) acc[mi][nj][q] = 0.f;

        const uint32_t* bsrc = &g_e16[(size_t)(n0 + sr) * 256 + sg * 4];

        // stage B chunk 0 into buf 0
        uint4 pb = *reinterpret_cast<const uint4*>(bsrc);
        *reinterpret_cast<uint4*>(sBc + sts_off) = pb;
        __syncthreads();

        for (int c = 0; c < NCH; c++) {
            const int cur = c & 1;
            if (c + 1 < NCH)
                pb = *reinterpret_cast<const uint4*>(bsrc + (c + 1) * 16);

            const uint32_t bufA = sAb + c * 8192;
            const uint32_t bufB = sBb + cur * 8192;
#pragma unroll
            for (int ks = 0; ks < 2; ks++) {
                uint32_t B[4];
                ldsm_x4(B, bufB + swz_grp(brow, 2 * ks + bg_off));
#pragma unroll
                for (int mi = 0; mi < 4; mi++) {
                    uint32_t A[4];
                    ldsm_x4(A, bufA + swz_grp(wm + mi * 16 + arow_off, 2 * ks + ag_off));
                    mma_f16(acc[mi][0], A[0], A[1], A[2], A[3], B[0], B[1]);
                    mma_f16(acc[mi][1], A[0], A[1], A[2], A[3], B[2], B[3]);
                }
            }

            if (c + 1 < NCH)
                *reinterpret_cast<uint4*>(sBc + (cur ^ 1) * 8192 + sts_off) = pb;
            __syncthreads();
        }

        // ---- epilogue: ref-rounding score + tile top-2 + smem merge ----
#pragma unroll
        for (int mi = 0; mi < 4; mi++) {
#pragma unroll
            for (int h = 0; h < 2; h++) {
                int row = wm + mi * 16 + lr4 + 8 * h;
                float znv = znr[row];
                float b = FLT_MAX, b2v = FLT_MAX;
                int   bi = 0;
#pragma unroll
                for (int nj = 0; nj < 2; nj++) {
                    int ce = wn + nj * 8 + 2 * lc;
                    float en0 = sen[ce], en1 = sen[ce + 1];
                    float s0 = __fsub_rn(__fadd_rn(znv, en0), __fmul_rn(2.0f, acc[mi][nj][h * 2]));
                    float s1 = __fsub_rn(__fadd_rn(znv, en1), __fmul_rn(2.0f, acc[mi][nj][h * 2 + 1]));
                    int cb = n0 + ce;
                    if (s0 < b) { b2v = b; b = s0; bi = cb; }
                    else if (s0 < b2v) b2v = s0;
                    if (s1 < b) { b2v = b; b = s1; bi = cb + 1; }
                    else if (s1 < b2v) b2v = s1;
                }
#pragma unroll
                for (int off = 1; off <= 2; off <<= 1) {
                    float vb  = __shfl_xor_sync(0xffffffffu, b,   off);
                    float vb2 = __shfl_xor_sync(0xffffffffu, b2v, off);
                    int   vi  = __shfl_xor_sync(0xffffffffu, bi,  off);
                    if (vb < b) { b2v = fminf(b, vb2); b = vb; bi = vi; }
                    else if (vb > b) { b2v = fminf(b2v, vb); }
                    else { bi = min(bi, vi); b2v = vb; }
                }
                if (lc == 0) {
                    int s = row * 8 + wcol;
                    float ob = sbest[s], ob2 = sb2[s];
                    int   oi = sidn[s];
                    if (b < ob)      { sbest[s] = b;  sb2[s] = fminf(ob, b2v);  sidn[s] = bi; }
                    else if (b > ob) {                sb2[s] = fminf(ob2, b);                 }
                    else             {                sb2[s] = ob;              sidn[s] = min(oi, bi); }
                }
            }
        }
        __syncthreads();   // slots settled; sen/B bufs safe for next tile
    }

    // ---- final per-row merge + flag ----
    if (t < 128) {
        float b  = sbest[t * 8];
        float bb = sb2  [t * 8];
        int   bi = sidn [t * 8];
#pragma unroll
        for (int x = 1; x < 8; x++) {
            float v  = sbest[t * 8 + x];
            float v2 = sb2  [t * 8 + x];
            int   vi = sidn [t * 8 + x];
            if (v < b) { bb = fminf(b, v2); b = v; bi = vi; }
            else if (v > b) { bb = fminf(bb, v); }
            else { bi = min(bi, vi); bb = v; }
        }
        srow[t] = bi;
        if (__fsub_rn(bb, b) < MARGIN) {
            int row = row0 + t;
            g_best[row] = ~0ULL;
            int p = atomicAdd(&g_flagcnt, 1);
            g_flagrows[p] = row;
        }
    }
    __syncthreads();

    // ---- gather: out[row] = emb[idx] (flagged rows fixed later) ----
    float4*       out4 = reinterpret_cast<float4*>(out + (size_t)row0 * DIMS);
    const float4* emb4 = reinterpret_cast<const float4*>(emb);
    for (int v = t; v < 128 * (DIMS / 4); v += 512) {
        int r  = v >> 7;
        int c4 = v & 127;
        out4[(size_t)r * 128 + c4] = emb4[(size_t)srow[r] * 128 + c4];
    }
}

// ---------------------------------------------------------------------------
// Exact fallback: R2-identical arithmetic, 128 flagged rows x 128 codes/task
// ---------------------------------------------------------------------------
__global__ __launch_bounds__(256)
void vq_exact_kernel(const float* __restrict__ z,
                     const float* __restrict__ emb) {
    __shared__ float Zs[16 * 128];
    __shared__ float Es[16 * 128];
    __shared__ int   rlist[128];

    const int t  = threadIdx.x;
    const int tx = t & 15;    // 8 codes each
    const int ty = t >> 4;    // 8 rows each
    const int lr = t >> 2;    // staging row 0..63 (and +64)
    const int dq = t & 3;

    int cnt = g_flagcnt;
    if (cnt <= 0) return;
    int tb = (cnt + 127) >> 7;
    int total = tb * 8;

    for (int task = blockIdx.x; task < total; task += gridDim.x) {
        int rb = task >> 3;
        int cg = task & 7;
        int c0 = cg * 128;

        __syncthreads();
        if (t < 128) {
            int j = rb * 128 + t;
            rlist[t] = g_flagrows[j < cnt ? j : cnt - 1];
        }
        __syncthreads();

        int rows[8]; float zn[8];
#pragma unroll
        for (int i = 0; i < 8; i++) {
            rows[i] = rlist[ty * 8 + i];
            zn[i] = g_znorm[rows[i]];
        }
        float en[8];
#pragma unroll
        for (int j = 0; j < 8; j++) en[j] = g_enorm[c0 + tx * 8 + j];

        float acc[8][8];
#pragma unroll
        for (int i = 0; i < 8; i++)
#pragma unroll
            for (int j = 0; j < 8; j++) acc[i][j] = 0.f;

        for (int c = 0; c < 32; c++) {       // 32 x 16-float chunks, R2 ordering
            const int k0 = c * 16;
            float4 za = *reinterpret_cast<const float4*>(
                z + (size_t)rlist[lr] * DIMS + k0 + dq * 4);
            float4 zb = *reinterpret_cast<const float4*>(
                z + (size_t)rlist[lr + 64] * DIMS + k0 + dq * 4);
            float4 ea = *reinterpret_cast<const float4*>(
                emb + (size_t)(c0 + lr) * DIMS + k0 + dq * 4);
            float4 eb = *reinterpret_cast<const float4*>(
                emb + (size_t)(c0 + lr + 64) * DIMS + k0 + dq * 4);

            __syncthreads();
            Zs[(dq * 4 + 0) * 128 + lr] = za.x;
            Zs[(dq * 4 + 1) * 128 + lr] = za.y;
            Zs[(dq * 4 + 2) * 128 + lr] = za.z;
            Zs[(dq * 4 + 3) * 128 + lr] = za.w;
            Zs[(dq * 4 + 0) * 128 + lr + 64] = zb.x;
            Zs[(dq * 4 + 1) * 128 + lr + 64] = zb.y;
            Zs[(dq * 4 + 2) * 128 + lr + 64] = zb.z;
            Zs[(dq * 4 + 3) * 128 + lr + 64] = zb.w;
            Es[(dq * 4 + 0) * 128 + lr] = ea.x;
            Es[(dq * 4 + 1) * 128 + lr] = ea.y;
            Es[(dq * 4 + 2) * 128 + lr] = ea.z;
            Es[(dq * 4 + 3) * 128 + lr] = ea.w;
            Es[(dq * 4 + 0) * 128 + lr + 64] = eb.x;
            Es[(dq * 4 + 1) * 128 + lr + 64] = eb.y;
            Es[(dq * 4 + 2) * 128 + lr + 64] = eb.z;
            Es[(dq * 4 + 3) * 128 + lr + 64] = eb.w;
            __syncthreads();

#pragma unroll
            for (int k = 0; k < 16; k++) {
                float zf[8], ef[8];
                *reinterpret_cast<float4*>(zf)     = *reinterpret_cast<float4*>(&Zs[k * 128 + ty * 8]);
                *reinterpret_cast<float4*>(zf + 4) = *reinterpret_cast<float4*>(&Zs[k * 128 + ty * 8 + 4]);
                *reinterpret_cast<float4*>(ef)     = *reinterpret_cast<float4*>(&Es[k * 128 + tx * 8]);
                *reinterpret_cast<float4*>(ef + 4) = *reinterpret_cast<float4*>(&Es[k * 128 + tx * 8 + 4]);
#pragma unroll
                for (int i = 0; i < 8; i++)
#pragma unroll
                    for (int j = 0; j < 8; j++)
                        acc[i][j] = fmaf(zf[i], ef[j], acc[i][j]);
            }
        }

        // score + per-thread argmin + cross-lane packed min (tie -> lowest idx)
#pragma unroll
        for (int i = 0; i < 8; i++) {
            float bb = 3.4e38f;
            int   bi = 0;
#pragma unroll
            for (int j = 0; j < 8; j++) {
                float s = __fsub_rn(__fadd_rn(zn[i], en[j]),
                                    __fmul_rn(2.0f, acc[i][j]));
                if (s < bb) { bb = s; bi = c0 + tx * 8 + j; }
            }
            unsigned long long pk =
                ((unsigned long long)__float_as_uint(bb) << 32) | (unsigned)bi;
#pragma unroll
            for (int off = 1; off <= 8; off <<= 1) {
                unsigned long long o = __shfl_xor_sync(0xffffffffu, pk, off);
                if (o < pk) pk = o;
            }
            if (tx == 0) atomicMin(&g_best[rows[i]], pk);
        }
    }
}

// ---------------------------------------------------------------------------
// Fixup gather for flagged rows
// ---------------------------------------------------------------------------
__global__ void vq_fix_kernel(const float* __restrict__ emb,
                              float* __restrict__ out) {
    int cnt = g_flagcnt;
    for (int j = blockIdx.x; j < cnt; j += gridDim.x) {
        int row = g_flagrows[j];
        unsigned idx = (unsigned)(g_best[row] & 0xffffffffu);
        const float4* src = reinterpret_cast<const float4*>(emb + (size_t)idx * DIMS);
        float4*       dst = reinterpret_cast<float4*>(out + (size_t)row * DIMS);
        for (int v = threadIdx.x; v < DIMS / 4; v += blockDim.x)
            dst[v] = src[v];
    }
}

// ---------------------------------------------------------------------------
// Launch
// ---------------------------------------------------------------------------
extern "C" void kernel_launch(void* const* d_in, const int* in_sizes, int n_in,
                              void* d_out, int out_size) {
    const float* z   = (const float*)d_in[0];   // [32,2048,512] fp32
    const float* emb = (const float*)d_in[1];   // [1024,512] fp32
    float* out = (float*)d_out;

    cudaFuncSetAttribute(vq_mma_kernel,
                         cudaFuncAttributeMaxDynamicSharedMemorySize, SM_DYN);

    econv_kernel<<<(CODES * 32 + 255) / 256, 256>>>(emb);   // also resets flagcnt
    zconv_kernel<<<(NROWS * 32 + 255) / 256, 256>>>(z);
    vq_mma_kernel<<<NROWS / MT, 512, SM_DYN>>>(emb, out);
    vq_exact_kernel<<<1024, 256>>>(z, emb);
    vq_fix_kernel<<<256, 128>>>(emb, out);
}

// round 11
// speedup vs baseline: 1.6501x; 1.0157x over previous
#include <cuda_runtime.h>
#include <cuda_fp16.h>
#include <cstdint>
#include <cfloat>

// Problem constants
#define NROWS 65536   // 32 * 2048
#define DIMS  512
#define CODES 1024

#define MT   128      // rows per CTA (TC kernel)
#define NT2  256      // codes per tile
#define KC   32       // K floats per chunk (fp16: 16 u32 per row)
#define NCH  (DIMS / KC)     // 16 chunks
#define NTL  (CODES / NT2)   // 4 tiles

#define MARGIN 2.0e-4f       // ~13 sigma of fp16 score error

// Scratch (device globals — allocation is forbidden)
__device__ float g_enorm[CODES];
__device__ float g_znorm[NROWS];
__device__ int   g_flagcnt;
__device__ int   g_flagrows[NROWS];
__device__ unsigned long long g_best[NROWS];
__device__ uint32_t g_z16[NROWS * DIMS / 2];   // 64 MB fp16-packed z
__device__ uint32_t g_e16[CODES * DIMS / 2];   // 1 MB fp16-packed emb

// ---------------------------------------------------------------------------
// Helpers
// ---------------------------------------------------------------------------
__device__ __forceinline__ void mma_f16(float* c,
                                        uint32_t a0, uint32_t a1, uint32_t a2, uint32_t a3,
                                        uint32_t b0, uint32_t b1) {
    asm volatile(
        "mma.sync.aligned.m16n8k16.row.col.f32.f16.f16.f32 "
        "{%0,%1,%2,%3}, {%4,%5,%6,%7}, {%8,%9}, {%0,%1,%2,%3};"
        : "+f"(c[0]), "+f"(c[1]), "+f"(c[2]), "+f"(c[3])
        : "r"(a0), "r"(a1), "r"(a2), "r"(a3), "r"(b0), "r"(b1));
}

__device__ __forceinline__ void ldsm_x4(uint32_t* f, uint32_t addr) {
    asm volatile(
        "ldmatrix.sync.aligned.m8n8.x4.shared.b16 {%0,%1,%2,%3}, [%4];"
        : "=r"(f[0]), "=r"(f[1]), "=r"(f[2]), "=r"(f[3]) : "r"(addr));
}

// byte offset of the 16B group (row r, u32-group g) in a swizzled [rows][16]-u32 tile
__device__ __forceinline__ uint32_t swz_grp(int r, int g) {
    int xr = (r >> 1) & 3;
    return (uint32_t)(((r << 4) + (((g ^ xr) & 3) << 2)) << 2);
}

__device__ __forceinline__ uint32_t pack_h2(float lo, float hi) {
    __half2 p = __float22half2_rn(make_float2(lo, hi));   // .x -> low 16 bits
    return *reinterpret_cast<uint32_t*>(&p);
}

// ---------------------------------------------------------------------------
// Convert kernels: fp32 -> packed fp16 globals, fused fp64 norms
// ---------------------------------------------------------------------------
__global__ void econv_kernel(const float* __restrict__ emb) {
    if (blockIdx.x == 0 && threadIdx.x == 0) g_flagcnt = 0;
    int warp = (blockIdx.x * blockDim.x + threadIdx.x) >> 5;
    int lane = threadIdx.x & 31;
    if (warp >= CODES) return;
    const float4* row = reinterpret_cast<const float4*>(emb + (size_t)warp * DIMS);
    double s = 0.0;
#pragma unroll
    for (int i = 0; i < 4; i++) {
        int j = lane + i * 32;
        float4 v = row[j];
        s += (double)v.x * v.x + (double)v.y * v.y
           + (double)v.z * v.z + (double)v.w * v.w;
        uint2 w = make_uint2(pack_h2(v.x, v.y), pack_h2(v.z, v.w));
        *reinterpret_cast<uint2*>(&g_e16[(size_t)warp * 256 + j * 2]) = w;
    }
#pragma unroll
    for (int off = 16; off > 0; off >>= 1)
        s += __shfl_xor_sync(0xffffffffu, s, off);
    if (lane == 0) g_enorm[warp] = (float)s;
}

__global__ void zconv_kernel(const float* __restrict__ z) {
    int warp = (blockIdx.x * blockDim.x + threadIdx.x) >> 5;
    int lane = threadIdx.x & 31;
    if (warp >= NROWS) return;
    const float4* row = reinterpret_cast<const float4*>(z + (size_t)warp * DIMS);
    double s = 0.0;
#pragma unroll
    for (int i = 0; i < 4; i++) {
        int j = lane + i * 32;
        float4 v = row[j];
        s += (double)v.x * v.x + (double)v.y * v.y
           + (double)v.z * v.z + (double)v.w * v.w;
        uint2 w = make_uint2(pack_h2(v.x, v.y), pack_h2(v.z, v.w));
        *reinterpret_cast<uint2*>(&g_z16[(size_t)warp * 256 + j * 2]) = w;
    }
#pragma unroll
    for (int off = 16; off > 0; off >>= 1)
        s += __shfl_xor_sync(0xffffffffu, s, off);
    if (lane == 0) g_znorm[warp] = (float)s;
}

// ---------------------------------------------------------------------------
// TC kernel: fp16 mma.sync (k16), A resident, B dbuf, N-tile = 256
// 512 threads: 16 warps = 2 (M: 64 rows) x 8 (N: 32 codes)
// Dynamic smem: A = 16 x 8KB = 128KB; B dbuf = 2 x 16KB at +128KB
// ---------------------------------------------------------------------------
#define SM_A_BYTES (NCH * 8192)              // 131072
#define SM_DYN     (SM_A_BYTES + 2 * 16384)  // 163840

extern __shared__ uint32_t dsm[];

__global__ __launch_bounds__(512, 1)
void vq_mma_kernel(const float* __restrict__ emb,
                   float* __restrict__ out) {
    __shared__ float znr[128];
    __shared__ float sen[NT2];
    __shared__ float sbest[128 * 8];
    __shared__ float sb2  [128 * 8];
    __shared__ int   sidn [128 * 8];
    __shared__ int   srow [128];

    const int t    = threadIdx.x;
    const int lane = t & 31;
    const int wid  = t >> 5;
    const int row0 = blockIdx.x * MT;
    const int wm   = (wid & 1) * 64;
    const int wcol = wid >> 1;          // 0..7
    const int wn   = wcol * 32;
    const int lr4  = lane >> 2;
    const int lc   = lane & 3;

    // ldmatrix per-lane address components
    const int m8 = lane >> 3, l7 = lane & 7;
    const int arow_off = ((m8 & 1) << 3) + l7;   // + wm + mi*16
    const int ag_off   = m8 >> 1;                // + 2*ks
    const int brow     = wn + ((m8 >> 1) << 3) + l7;
    const int bg_off   = m8 & 1;                 // + 2*ks

    const uint32_t sAb = (uint32_t)__cvta_generic_to_shared(dsm);
    const uint32_t sBb = sAb + SM_A_BYTES;

    // staging mapping: r = t>>2 (0..127), 16B group = t&3
    const int sr = t >> 2, sg = t & 3;
    const uint32_t stsA = swz_grp(sr, sg);
    const uint32_t stsB0 = swz_grp(sr, sg);
    const uint32_t stsB1 = swz_grp(sr + 128, sg);

    for (int i = t; i < 128 * 8; i += 512) {
        sbest[i] = FLT_MAX; sb2[i] = FLT_MAX; sidn[i] = 0;
    }
    if (t < 128) znr[t] = g_znorm[row0 + t];

    // ---- load resident A: 16 chunk-tiles, 1 uint4 per thread per chunk ----
    {
        const uint32_t* zsrc = &g_z16[(size_t)(row0 + sr) * 256 + sg * 4];
        char* sAc = reinterpret_cast<char*>(dsm);
#pragma unroll
        for (int c = 0; c < NCH; c++) {
            uint4 v = *reinterpret_cast<const uint4*>(zsrc + c * 16);
            *reinterpret_cast<uint4*>(sAc + c * 8192 + stsA) = v;
        }
    }
    __syncthreads();

    char* sBc = reinterpret_cast<char*>(dsm) + SM_A_BYTES;

    for (int nt = 0; nt < NTL; nt++) {
        const int n0 = nt * NT2;
        if (t < NT2 / 4)
            reinterpret_cast<float4*>(sen)[t] =
                reinterpret_cast<const float4*>(&g_enorm[n0])[t];

        float acc[4][4][4];
#pragma unroll
        for (int mi = 0; mi < 4; mi++)
#pragma unroll
            for (int nj = 0; nj < 4; nj++)
#pragma unroll
                for (int q = 0; q < 4; q++) acc[mi][nj][q] = 0.f;

        const uint32_t* bsrc0 = &g_e16[(size_t)(n0 + sr) * 256 + sg * 4];
        const uint32_t* bsrc1 = bsrc0 + 128 * 256;

        uint4 pb0 = *reinterpret_cast<const uint4*>(bsrc0);
        uint4 pb1 = *reinterpret_cast<const uint4*>(bsrc1);
        *reinterpret_cast<uint4*>(sBc + stsB0) = pb0;
        *reinterpret_cast<uint4*>(sBc + stsB1) = pb1;
        __syncthreads();

        for (int c = 0; c < NCH; c++) {
            const int cur = c & 1;
            if (c + 1 < NCH) {
                pb0 = *reinterpret_cast<const uint4*>(bsrc0 + (c + 1) * 16);
                pb1 = *reinterpret_cast<const uint4*>(bsrc1 + (c + 1) * 16);
            }

            const uint32_t bufA = sAb + c * 8192;
            const uint32_t bufB = sBb + cur * 16384;
#pragma unroll
            for (int ks = 0; ks < 2; ks++) {
                uint32_t B0[4], B1[4];
                ldsm_x4(B0, bufB + swz_grp(brow,      2 * ks + bg_off));
                ldsm_x4(B1, bufB + swz_grp(brow + 16, 2 * ks + bg_off));
#pragma unroll
                for (int mi = 0; mi < 4; mi++) {
                    uint32_t A[4];
                    ldsm_x4(A, bufA + swz_grp(wm + mi * 16 + arow_off, 2 * ks + ag_off));
                    mma_f16(acc[mi][0], A[0], A[1], A[2], A[3], B0[0], B0[1]);
                    mma_f16(acc[mi][1], A[0], A[1], A[2], A[3], B0[2], B0[3]);
                    mma_f16(acc[mi][2], A[0], A[1], A[2], A[3], B1[0], B1[1]);
                    mma_f16(acc[mi][3], A[0], A[1], A[2], A[3], B1[2], B1[3]);
                }
            }

            if (c + 1 < NCH) {
                char* nbuf = sBc + (cur ^ 1) * 16384;
                *reinterpret_cast<uint4*>(nbuf + stsB0) = pb0;
                *reinterpret_cast<uint4*>(nbuf + stsB1) = pb1;
            }
            __syncthreads();
        }

        // ---- epilogue: ref-rounding score + tile top-2 + smem merge ----
#pragma unroll
        for (int mi = 0; mi < 4; mi++) {
#pragma unroll
            for (int h = 0; h < 2; h++) {
                int row = wm + mi * 16 + lr4 + 8 * h;
                float znv = znr[row];
                float b = FLT_MAX, b2v = FLT_MAX;
                int   bi = 0;
#pragma unroll
                for (int nj = 0; nj < 4; nj++) {
                    int ce = wn + nj * 8 + 2 * lc;
                    float en0 = sen[ce], en1 = sen[ce + 1];
                    float s0 = __fsub_rn(__fadd_rn(znv, en0), __fmul_rn(2.0f, acc[mi][nj][h * 2]));
                    float s1 = __fsub_rn(__fadd_rn(znv, en1), __fmul_rn(2.0f, acc[mi][nj][h * 2 + 1]));
                    int cb = n0 + ce;
                    if (s0 < b) { b2v = b; b = s0; bi = cb; }
                    else if (s0 < b2v) b2v = s0;
                    if (s1 < b) { b2v = b; b = s1; bi = cb + 1; }
                    else if (s1 < b2v) b2v = s1;
                }
#pragma unroll
                for (int off = 1; off <= 2; off <<= 1) {
                    float vb  = __shfl_xor_sync(0xffffffffu, b,   off);
                    float vb2 = __shfl_xor_sync(0xffffffffu, b2v, off);
                    int   vi  = __shfl_xor_sync(0xffffffffu, bi,  off);
                    if (vb < b) { b2v = fminf(b, vb2); b = vb; bi = vi; }
                    else if (vb > b) { b2v = fminf(b2v, vb); }
                    else { bi = min(bi, vi); b2v = vb; }
                }
                if (lc == 0) {
                    int s = row * 8 + wcol;
                    float ob = sbest[s], ob2 = sb2[s];
                    int   oi = sidn[s];
                    if (b < ob)      { sbest[s] = b;  sb2[s] = fminf(ob, b2v);  sidn[s] = bi; }
                    else if (b > ob) {                sb2[s] = fminf(ob2, b);                 }
                    else             {                sb2[s] = ob;              sidn[s] = min(oi, bi); }
                }
            }
        }
        __syncthreads();
    }

    // ---- final per-row merge + flag ----
    if (t < 128) {
        float b  = sbest[t * 8];
        float bb = sb2  [t * 8];
        int   bi = sidn [t * 8];
#pragma unroll
        for (int x = 1; x < 8; x++) {
            float v  = sbest[t * 8 + x];
            float v2 = sb2  [t * 8 + x];
            int   vi = sidn [t * 8 + x];
            if (v < b) { bb = fminf(b, v2); b = v; bi = vi; }
            else if (v > b) { bb = fminf(bb, v); }
            else { bi = min(bi, vi); bb = v; }
        }
        srow[t] = bi;
        if (__fsub_rn(bb, b) < MARGIN) {
            int row = row0 + t;
            g_best[row] = ~0ULL;
            int p = atomicAdd(&g_flagcnt, 1);
            g_flagrows[p] = row;
        }
    }
    __syncthreads();

    // ---- gather: out[row] = emb[idx] (flagged rows fixed later) ----
    float4*       out4 = reinterpret_cast<float4*>(out + (size_t)row0 * DIMS);
    const float4* emb4 = reinterpret_cast<const float4*>(emb);
    for (int v = t; v < 128 * (DIMS / 4); v += 512) {
        int r  = v >> 7;
        int c4 = v & 127;
        out4[(size_t)r * 128 + c4] = emb4[(size_t)srow[r] * 128 + c4];
    }
}

// ---------------------------------------------------------------------------
// Exact fallback: R2-identical ascending-k fmaf chains for flagged rows.
// Task = 32 rows x 128 codes (small -> low serial latency, high parallelism)
// ---------------------------------------------------------------------------
__global__ __launch_bounds__(256)
void vq_exact_kernel(const float* __restrict__ z,
                     const float* __restrict__ emb) {
    __shared__ float Zs[16 * 32];
    __shared__ float Es[16 * 128];
    __shared__ int   rlist[32];

    const int t  = threadIdx.x;
    const int tx = t & 15;    // 8 codes each
    const int ty = t >> 4;    // 2 rows each (16 groups)

    int cnt = g_flagcnt;
    if (cnt <= 0) return;
    int tb = (cnt + 31) >> 5;
    int total = tb * 8;

    for (int task = blockIdx.x; task < total; task += gridDim.x) {
        int rb = task >> 3;
        int cg = task & 7;
        int c0 = cg * 128;

        __syncthreads();
        if (t < 32) {
            int j = rb * 32 + t;
            rlist[t] = g_flagrows[j < cnt ? j : cnt - 1];
        }
        __syncthreads();

        int rows[2]; float zn[2];
#pragma unroll
        for (int i = 0; i < 2; i++) {
            rows[i] = rlist[ty * 2 + i];
            zn[i] = g_znorm[rows[i]];
        }
        float en[8];
#pragma unroll
        for (int j = 0; j < 8; j++) en[j] = g_enorm[c0 + tx * 8 + j];

        float acc[2][8];
#pragma unroll
        for (int i = 0; i < 2; i++)
#pragma unroll
            for (int j = 0; j < 8; j++) acc[i][j] = 0.f;

        for (int c = 0; c < 32; c++) {       // 32 x 16-float chunks, R2 ordering
            const int k0 = c * 16;
            __syncthreads();
            if (t < 128) {   // stage Z: 32 rows x 16 K, [k][row]
                int r = t >> 2, q = t & 3;
                float4 x = *reinterpret_cast<const float4*>(
                    z + (size_t)rlist[r] * DIMS + k0 + q * 4);
                Zs[(q * 4 + 0) * 32 + r] = x.x;
                Zs[(q * 4 + 1) * 32 + r] = x.y;
                Zs[(q * 4 + 2) * 32 + r] = x.z;
                Zs[(q * 4 + 3) * 32 + r] = x.w;
            }
#pragma unroll
            for (int i = 0; i < 2; i++) {    // stage E: 128 codes x 16 K
                int v = t + 256 * i;
                int r = v >> 2, q = v & 3;
                float4 x = *reinterpret_cast<const float4*>(
                    emb + (size_t)(c0 + r) * DIMS + k0 + q * 4);
                Es[(q * 4 + 0) * 128 + r] = x.x;
                Es[(q * 4 + 1) * 128 + r] = x.y;
                Es[(q * 4 + 2) * 128 + r] = x.z;
                Es[(q * 4 + 3) * 128 + r] = x.w;
            }
            __syncthreads();

#pragma unroll
            for (int k = 0; k < 16; k++) {
                float zf[2], ef[8];
                zf[0] = Zs[k * 32 + ty * 2];
                zf[1] = Zs[k * 32 + ty * 2 + 1];
                *reinterpret_cast<float4*>(ef)     = *reinterpret_cast<float4*>(&Es[k * 128 + tx * 8]);
                *reinterpret_cast<float4*>(ef + 4) = *reinterpret_cast<float4*>(&Es[k * 128 + tx * 8 + 4]);
#pragma unroll
                for (int i = 0; i < 2; i++)
#pragma unroll
                    for (int j = 0; j < 8; j++)
                        acc[i][j] = fmaf(zf[i], ef[j], acc[i][j]);
            }
        }

        // score + per-thread argmin + cross-lane packed min (tie -> lowest idx)
#pragma unroll
        for (int i = 0; i < 2; i++) {
            float bb = 3.4e38f;
            int   bi = 0;
#pragma unroll
            for (int j = 0; j < 8; j++) {
                float s = __fsub_rn(__fadd_rn(zn[i], en[j]),
                                    __fmul_rn(2.0f, acc[i][j]));
                if (s < bb) { bb = s; bi = c0 + tx * 8 + j; }
            }
            unsigned long long pk =
                ((unsigned long long)__float_as_uint(bb) << 32) | (unsigned)bi;
#pragma unroll
            for (int off = 1; off <= 8; off <<= 1) {
                unsigned long long o = __shfl_xor_sync(0xffffffffu, pk, off);
                if (o < pk) pk = o;
            }
            if (tx == 0) atomicMin(&g_best[rows[i]], pk);
        }
    }
}

// ---------------------------------------------------------------------------
// Fixup gather for flagged rows
// ---------------------------------------------------------------------------
__global__ void vq_fix_kernel(const float* __restrict__ emb,
                              float* __restrict__ out) {
    int cnt = g_flagcnt;
    for (int j = blockIdx.x; j < cnt; j += gridDim.x) {
        int row = g_flagrows[j];
        unsigned idx = (unsigned)(g_best[row] & 0xffffffffu);
        const float4* src = reinterpret_cast<const float4*>(emb + (size_t)idx * DIMS);
        float4*       dst = reinterpret_cast<float4*>(out + (size_t)row * DIMS);
        for (int v = threadIdx.x; v < DIMS / 4; v += blockDim.x)
            dst[v] = src[v];
    }
}

// ---------------------------------------------------------------------------
// Launch
// ---------------------------------------------------------------------------
extern "C" void kernel_launch(void* const* d_in, const int* in_sizes, int n_in,
                              void* d_out, int out_size) {
    const float* z   = (const float*)d_in[0];   // [32,2048,512] fp32
    const float* emb = (const float*)d_in[1];   // [1024,512] fp32
    float* out = (float*)d_out;

    cudaFuncSetAttribute(vq_mma_kernel,
                         cudaFuncAttributeMaxDynamicSharedMemorySize, SM_DYN);

    econv_kernel<<<(CODES * 32 + 255) / 256, 256>>>(emb);   // also resets flagcnt
    zconv_kernel<<<(NROWS * 32 + 255) / 256, 256>>>(z);
    vq_mma_kernel<<<NROWS / MT, 512, SM_DYN>>>(emb, out);
    vq_exact_kernel<<<1024, 256>>>(z, emb);
    vq_fix_kernel<<<1024, 128>>>(emb, out);
}

// round 12
// speedup vs baseline: 1.9968x; 1.2101x over previous
#include <cuda_runtime.h>
#include <cuda_fp16.h>
#include <cstdint>
#include <cfloat>

// Problem constants
#define NROWS 65536   // 32 * 2048
#define DIMS  512
#define CODES 1024

#define MT   128      // rows per CTA (TC kernel)
#define NT2  256      // codes per tile
#define KC   32       // K floats per chunk (fp16: 16 u32 per row)
#define NCH  (DIMS / KC)     // 16 chunks
#define NTL  (CODES / NT2)   // 4 tiles

#define MARGIN 2.0e-4f       // ~13 sigma of fp16 score error

// Scratch (device globals — allocation is forbidden)
__device__ float g_enorm[CODES];
__device__ float g_znorm[NROWS];
__device__ int   g_flagcnt;
__device__ int   g_flagrows[NROWS];
__device__ unsigned long long g_best[NROWS];
__device__ uint32_t g_z16[NROWS * DIMS / 2];   // 64 MB fp16-packed z
__device__ uint32_t g_e16[CODES * DIMS / 2];   // 1 MB fp16-packed emb

// ---------------------------------------------------------------------------
// Helpers
// ---------------------------------------------------------------------------
__device__ __forceinline__ void mma_f16(float* c,
                                        uint32_t a0, uint32_t a1, uint32_t a2, uint32_t a3,
                                        uint32_t b0, uint32_t b1) {
    asm volatile(
        "mma.sync.aligned.m16n8k16.row.col.f32.f16.f16.f32 "
        "{%0,%1,%2,%3}, {%4,%5,%6,%7}, {%8,%9}, {%0,%1,%2,%3};"
        : "+f"(c[0]), "+f"(c[1]), "+f"(c[2]), "+f"(c[3])
        : "r"(a0), "r"(a1), "r"(a2), "r"(a3), "r"(b0), "r"(b1));
}

__device__ __forceinline__ void ldsm_x4(uint32_t* f, uint32_t addr) {
    asm volatile(
        "ldmatrix.sync.aligned.m8n8.x4.shared.b16 {%0,%1,%2,%3}, [%4];"
        : "=r"(f[0]), "=r"(f[1]), "=r"(f[2]), "=r"(f[3]) : "r"(addr));
}

// byte offset of the 16B group (row r, u32-group g) in a swizzled [rows][16]-u32 tile
__device__ __forceinline__ uint32_t swz_grp(int r, int g) {
    int xr = (r >> 1) & 3;
    return (uint32_t)(((r << 4) + (((g ^ xr) & 3) << 2)) << 2);
}

__device__ __forceinline__ uint32_t pack_h2(float lo, float hi) {
    __half2 p = __float22half2_rn(make_float2(lo, hi));   // .x -> low 16 bits
    return *reinterpret_cast<uint32_t*>(&p);
}

// ---------------------------------------------------------------------------
// Convert kernels: fp32 -> packed fp16 globals, fused fp64 norms
// ---------------------------------------------------------------------------
__global__ void econv_kernel(const float* __restrict__ emb) {
    if (blockIdx.x == 0 && threadIdx.x == 0) g_flagcnt = 0;
    int warp = (blockIdx.x * blockDim.x + threadIdx.x) >> 5;
    int lane = threadIdx.x & 31;
    if (warp >= CODES) return;
    const float4* row = reinterpret_cast<const float4*>(emb + (size_t)warp * DIMS);
    double s = 0.0;
#pragma unroll
    for (int i = 0; i < 4; i++) {
        int j = lane + i * 32;
        float4 v = row[j];
        s += (double)v.x * v.x + (double)v.y * v.y
           + (double)v.z * v.z + (double)v.w * v.w;
        uint2 w = make_uint2(pack_h2(v.x, v.y), pack_h2(v.z, v.w));
        *reinterpret_cast<uint2*>(&g_e16[(size_t)warp * 256 + j * 2]) = w;
    }
#pragma unroll
    for (int off = 16; off > 0; off >>= 1)
        s += __shfl_xor_sync(0xffffffffu, s, off);
    if (lane == 0) g_enorm[warp] = (float)s;
}

__global__ void zconv_kernel(const float* __restrict__ z) {
    int warp = (blockIdx.x * blockDim.x + threadIdx.x) >> 5;
    int lane = threadIdx.x & 31;
    if (warp >= NROWS) return;
    const float4* row = reinterpret_cast<const float4*>(z + (size_t)warp * DIMS);
    double s = 0.0;
#pragma unroll
    for (int i = 0; i < 4; i++) {
        int j = lane + i * 32;
        float4 v = row[j];
        s += (double)v.x * v.x + (double)v.y * v.y
           + (double)v.z * v.z + (double)v.w * v.w;
        uint2 w = make_uint2(pack_h2(v.x, v.y), pack_h2(v.z, v.w));
        *reinterpret_cast<uint2*>(&g_z16[(size_t)warp * 256 + j * 2]) = w;
    }
#pragma unroll
    for (int off = 16; off > 0; off >>= 1)
        s += __shfl_xor_sync(0xffffffffu, s, off);
    if (lane == 0) g_znorm[warp] = (float)s;
}

// ---------------------------------------------------------------------------
// TC kernel: fp16 mma.sync (k16), A resident, B dbuf, N-tile = 256 (unchanged)
// ---------------------------------------------------------------------------
#define SM_A_BYTES (NCH * 8192)              // 131072
#define SM_DYN     (SM_A_BYTES + 2 * 16384)  // 163840

extern __shared__ uint32_t dsm[];

__global__ __launch_bounds__(512, 1)
void vq_mma_kernel(const float* __restrict__ emb,
                   float* __restrict__ out) {
    __shared__ float znr[128];
    __shared__ float sen[NT2];
    __shared__ float sbest[128 * 8];
    __shared__ float sb2  [128 * 8];
    __shared__ int   sidn [128 * 8];
    __shared__ int   srow [128];

    const int t    = threadIdx.x;
    const int lane = t & 31;
    const int wid  = t >> 5;
    const int row0 = blockIdx.x * MT;
    const int wm   = (wid & 1) * 64;
    const int wcol = wid >> 1;          // 0..7
    const int wn   = wcol * 32;
    const int lr4  = lane >> 2;
    const int lc   = lane & 3;

    const int m8 = lane >> 3, l7 = lane & 7;
    const int arow_off = ((m8 & 1) << 3) + l7;
    const int ag_off   = m8 >> 1;
    const int brow     = wn + ((m8 >> 1) << 3) + l7;
    const int bg_off   = m8 & 1;

    const uint32_t sAb = (uint32_t)__cvta_generic_to_shared(dsm);
    const uint32_t sBb = sAb + SM_A_BYTES;

    const int sr = t >> 2, sg = t & 3;
    const uint32_t stsA = swz_grp(sr, sg);
    const uint32_t stsB0 = swz_grp(sr, sg);
    const uint32_t stsB1 = swz_grp(sr + 128, sg);

    for (int i = t; i < 128 * 8; i += 512) {
        sbest[i] = FLT_MAX; sb2[i] = FLT_MAX; sidn[i] = 0;
    }
    if (t < 128) znr[t] = g_znorm[row0 + t];

    {
        const uint32_t* zsrc = &g_z16[(size_t)(row0 + sr) * 256 + sg * 4];
        char* sAc = reinterpret_cast<char*>(dsm);
#pragma unroll
        for (int c = 0; c < NCH; c++) {
            uint4 v = *reinterpret_cast<const uint4*>(zsrc + c * 16);
            *reinterpret_cast<uint4*>(sAc + c * 8192 + stsA) = v;
        }
    }
    __syncthreads();

    char* sBc = reinterpret_cast<char*>(dsm) + SM_A_BYTES;

    for (int nt = 0; nt < NTL; nt++) {
        const int n0 = nt * NT2;
        if (t < NT2 / 4)
            reinterpret_cast<float4*>(sen)[t] =
                reinterpret_cast<const float4*>(&g_enorm[n0])[t];

        float acc[4][4][4];
#pragma unroll
        for (int mi = 0; mi < 4; mi++)
#pragma unroll
            for (int nj = 0; nj < 4; nj++)
#pragma unroll
                for (int q = 0; q < 4; q++) acc[mi][nj][q] = 0.f;

        const uint32_t* bsrc0 = &g_e16[(size_t)(n0 + sr) * 256 + sg * 4];
        const uint32_t* bsrc1 = bsrc0 + 128 * 256;

        uint4 pb0 = *reinterpret_cast<const uint4*>(bsrc0);
        uint4 pb1 = *reinterpret_cast<const uint4*>(bsrc1);
        *reinterpret_cast<uint4*>(sBc + stsB0) = pb0;
        *reinterpret_cast<uint4*>(sBc + stsB1) = pb1;
        __syncthreads();

        for (int c = 0; c < NCH; c++) {
            const int cur = c & 1;
            if (c + 1 < NCH) {
                pb0 = *reinterpret_cast<const uint4*>(bsrc0 + (c + 1) * 16);
                pb1 = *reinterpret_cast<const uint4*>(bsrc1 + (c + 1) * 16);
            }

            const uint32_t bufA = sAb + c * 8192;
            const uint32_t bufB = sBb + cur * 16384;
#pragma unroll
            for (int ks = 0; ks < 2; ks++) {
                uint32_t B0[4], B1[4];
                ldsm_x4(B0, bufB + swz_grp(brow,      2 * ks + bg_off));
                ldsm_x4(B1, bufB + swz_grp(brow + 16, 2 * ks + bg_off));
#pragma unroll
                for (int mi = 0; mi < 4; mi++) {
                    uint32_t A[4];
                    ldsm_x4(A, bufA + swz_grp(wm + mi * 16 + arow_off, 2 * ks + ag_off));
                    mma_f16(acc[mi][0], A[0], A[1], A[2], A[3], B0[0], B0[1]);
                    mma_f16(acc[mi][1], A[0], A[1], A[2], A[3], B0[2], B0[3]);
                    mma_f16(acc[mi][2], A[0], A[1], A[2], A[3], B1[0], B1[1]);
                    mma_f16(acc[mi][3], A[0], A[1], A[2], A[3], B1[2], B1[3]);
                }
            }

            if (c + 1 < NCH) {
                char* nbuf = sBc + (cur ^ 1) * 16384;
                *reinterpret_cast<uint4*>(nbuf + stsB0) = pb0;
                *reinterpret_cast<uint4*>(nbuf + stsB1) = pb1;
            }
            __syncthreads();
        }

        // ---- epilogue: ref-rounding score + tile top-2 + smem merge ----
#pragma unroll
        for (int mi = 0; mi < 4; mi++) {
#pragma unroll
            for (int h = 0; h < 2; h++) {
                int row = wm + mi * 16 + lr4 + 8 * h;
                float znv = znr[row];
                float b = FLT_MAX, b2v = FLT_MAX;
                int   bi = 0;
#pragma unroll
                for (int nj = 0; nj < 4; nj++) {
                    int ce = wn + nj * 8 + 2 * lc;
                    float en0 = sen[ce], en1 = sen[ce + 1];
                    float s0 = __fsub_rn(__fadd_rn(znv, en0), __fmul_rn(2.0f, acc[mi][nj][h * 2]));
                    float s1 = __fsub_rn(__fadd_rn(znv, en1), __fmul_rn(2.0f, acc[mi][nj][h * 2 + 1]));
                    int cb = n0 + ce;
                    if (s0 < b) { b2v = b; b = s0; bi = cb; }
                    else if (s0 < b2v) b2v = s0;
                    if (s1 < b) { b2v = b; b = s1; bi = cb + 1; }
                    else if (s1 < b2v) b2v = s1;
                }
#pragma unroll
                for (int off = 1; off <= 2; off <<= 1) {
                    float vb  = __shfl_xor_sync(0xffffffffu, b,   off);
                    float vb2 = __shfl_xor_sync(0xffffffffu, b2v, off);
                    int   vi  = __shfl_xor_sync(0xffffffffu, bi,  off);
                    if (vb < b) { b2v = fminf(b, vb2); b = vb; bi = vi; }
                    else if (vb > b) { b2v = fminf(b2v, vb); }
                    else { bi = min(bi, vi); b2v = vb; }
                }
                if (lc == 0) {
                    int s = row * 8 + wcol;
                    float ob = sbest[s], ob2 = sb2[s];
                    int   oi = sidn[s];
                    if (b < ob)      { sbest[s] = b;  sb2[s] = fminf(ob, b2v);  sidn[s] = bi; }
                    else if (b > ob) {                sb2[s] = fminf(ob2, b);                 }
                    else             {                sb2[s] = ob;              sidn[s] = min(oi, bi); }
                }
            }
        }
        __syncthreads();
    }

    // ---- final per-row merge + flag ----
    if (t < 128) {
        float b  = sbest[t * 8];
        float bb = sb2  [t * 8];
        int   bi = sidn [t * 8];
#pragma unroll
        for (int x = 1; x < 8; x++) {
            float v  = sbest[t * 8 + x];
            float v2 = sb2  [t * 8 + x];
            int   vi = sidn [t * 8 + x];
            if (v < b) { bb = fminf(b, v2); b = v; bi = vi; }
            else if (v > b) { bb = fminf(bb, v); }
            else { bi = min(bi, vi); bb = v; }
        }
        srow[t] = bi;
        if (__fsub_rn(bb, b) < MARGIN) {
            int row = row0 + t;
            g_best[row] = ~0ULL;
            int p = atomicAdd(&g_flagcnt, 1);
            g_flagrows[p] = row;
        }
    }
    __syncthreads();

    // ---- gather ----
    float4*       out4 = reinterpret_cast<float4*>(out + (size_t)row0 * DIMS);
    const float4* emb4 = reinterpret_cast<const float4*>(emb);
    for (int v = t; v < 128 * (DIMS / 4); v += 512) {
        int r  = v >> 7;
        int c4 = v & 127;
        out4[(size_t)r * 128 + c4] = emb4[(size_t)srow[r] * 128 + c4];
    }
}

// ---------------------------------------------------------------------------
// Exact fallback: R2-identical ascending-k fmaf chains for flagged rows.
// Task = 128 rows x 64 codes: 16 tasks per 128-row block -> ~160 tasks total,
// per-thread 8x4 microtile (16k-FMA serial chain, 512 FMA per staged chunk)
// ---------------------------------------------------------------------------
__global__ __launch_bounds__(256)
void vq_exact_kernel(const float* __restrict__ z,
                     const float* __restrict__ emb) {
    __shared__ float Zs[16 * 128];
    __shared__ float Es[16 * 64];
    __shared__ int   rlist[128];

    const int t  = threadIdx.x;
    const int tx = t & 15;    // 4 codes each
    const int ty = t >> 4;    // 8 rows each (16 groups x 8 = 128 rows)
    const int lr = t >> 2;    // staging row 0..63 (and +64)
    const int dq = t & 3;

    int cnt = g_flagcnt;
    if (cnt <= 0) return;
    int tb = (cnt + 127) >> 7;
    int total = tb * 16;      // 16 code-groups of 64

    for (int task = blockIdx.x; task < total; task += gridDim.x) {
        int rb = task >> 4;
        int cg = task & 15;
        int c0 = cg * 64;

        __syncthreads();
        if (t < 128) {
            int j = rb * 128 + t;
            rlist[t] = g_flagrows[j < cnt ? j : cnt - 1];
        }
        __syncthreads();

        int rows[8]; float zn[8];
#pragma unroll
        for (int i = 0; i < 8; i++) {
            rows[i] = rlist[ty * 8 + i];
            zn[i] = g_znorm[rows[i]];
        }
        float en[4];
#pragma unroll
        for (int j = 0; j < 4; j++) en[j] = g_enorm[c0 + tx * 4 + j];

        float acc[8][4];
#pragma unroll
        for (int i = 0; i < 8; i++)
#pragma unroll
            for (int j = 0; j < 4; j++) acc[i][j] = 0.f;

        for (int c = 0; c < 32; c++) {       // 32 x 16-float chunks, R2 ordering
            const int k0 = c * 16;
            float4 za = *reinterpret_cast<const float4*>(
                z + (size_t)rlist[lr] * DIMS + k0 + dq * 4);
            float4 zb = *reinterpret_cast<const float4*>(
                z + (size_t)rlist[lr + 64] * DIMS + k0 + dq * 4);
            __syncthreads();
            Zs[(dq * 4 + 0) * 128 + lr] = za.x;
            Zs[(dq * 4 + 1) * 128 + lr] = za.y;
            Zs[(dq * 4 + 2) * 128 + lr] = za.z;
            Zs[(dq * 4 + 3) * 128 + lr] = za.w;
            Zs[(dq * 4 + 0) * 128 + lr + 64] = zb.x;
            Zs[(dq * 4 + 1) * 128 + lr + 64] = zb.y;
            Zs[(dq * 4 + 2) * 128 + lr + 64] = zb.z;
            Zs[(dq * 4 + 3) * 128 + lr + 64] = zb.w;
            if (t < 256) {   // stage E: 64 codes x 16 K = 256 float4, 1/thread
                int r = t >> 2, q = t & 3;
                float4 x = *reinterpret_cast<const float4*>(
                    emb + (size_t)(c0 + r) * DIMS + k0 + q * 4);
                Es[(q * 4 + 0) * 64 + r] = x.x;
                Es[(q * 4 + 1) * 64 + r] = x.y;
                Es[(q * 4 + 2) * 64 + r] = x.z;
                Es[(q * 4 + 3) * 64 + r] = x.w;
            }
            __syncthreads();

#pragma unroll
            for (int k = 0; k < 16; k++) {
                float zf[8], ef[4];
                *reinterpret_cast<float4*>(zf)     = *reinterpret_cast<float4*>(&Zs[k * 128 + ty * 8]);
                *reinterpret_cast<float4*>(zf + 4) = *reinterpret_cast<float4*>(&Zs[k * 128 + ty * 8 + 4]);
                *reinterpret_cast<float4*>(ef)     = *reinterpret_cast<float4*>(&Es[k * 64 + tx * 4]);
#pragma unroll
                for (int i = 0; i < 8; i++)
#pragma unroll
                    for (int j = 0; j < 4; j++)
                        acc[i][j] = fmaf(zf[i], ef[j], acc[i][j]);
            }
        }

        // score + per-thread argmin + cross-lane packed min (tie -> lowest idx)
#pragma unroll
        for (int i = 0; i < 8; i++) {
            float bb = 3.4e38f;
            int   bi = 0;
#pragma unroll
            for (int j = 0; j < 4; j++) {
                float s = __fsub_rn(__fadd_rn(zn[i], en[j]),
                                    __fmul_rn(2.0f, acc[i][j]));
                if (s < bb) { bb = s; bi = c0 + tx * 4 + j; }
            }
            unsigned long long pk =
                ((unsigned long long)__float_as_uint(bb) << 32) | (unsigned)bi;
#pragma unroll
            for (int off = 1; off <= 8; off <<= 1) {
                unsigned long long o = __shfl_xor_sync(0xffffffffu, pk, off);
                if (o < pk) pk = o;
            }
            if (tx == 0) atomicMin(&g_best[rows[i]], pk);
        }
    }
}

// ---------------------------------------------------------------------------
// Fixup gather for flagged rows
// ---------------------------------------------------------------------------
__global__ void vq_fix_kernel(const float* __restrict__ emb,
                              float* __restrict__ out) {
    int cnt = g_flagcnt;
    for (int j = blockIdx.x; j < cnt; j += gridDim.x) {
        int row = g_flagrows[j];
        unsigned idx = (unsigned)(g_best[row] & 0xffffffffu);
        const float4* src = reinterpret_cast<const float4*>(emb + (size_t)idx * DIMS);
        float4*       dst = reinterpret_cast<float4*>(out + (size_t)row * DIMS);
        for (int v = threadIdx.x; v < DIMS / 4; v += blockDim.x)
            dst[v] = src[v];
    }
}

// ---------------------------------------------------------------------------
// Launch
// ---------------------------------------------------------------------------
extern "C" void kernel_launch(void* const* d_in, const int* in_sizes, int n_in,
                              void* d_out, int out_size) {
    const float* z   = (const float*)d_in[0];   // [32,2048,512] fp32
    const float* emb = (const float*)d_in[1];   // [1024,512] fp32
    float* out = (float*)d_out;

    cudaFuncSetAttribute(vq_mma_kernel,
                         cudaFuncAttributeMaxDynamicSharedMemorySize, SM_DYN);

    econv_kernel<<<(CODES * 32 + 255) / 256, 256>>>(emb);   // also resets flagcnt
    zconv_kernel<<<(NROWS * 32 + 255) / 256, 256>>>(z);
    vq_mma_kernel<<<NROWS / MT, 512, SM_DYN>>>(emb, out);
    vq_exact_kernel<<<1024, 256>>>(z, emb);
    vq_fix_kernel<<<1024, 128>>>(emb, out);
}